// round 2
// baseline (speedup 1.0000x reference)
#include <cuda_runtime.h>
#include <math.h>

#define NNODES 100000
#define NEDGES 1600000
#define NB_SCAN 98   /* ceil(NNODES/1024) */

#define FMA2(c, a, b) asm("fma.rn.f32x2 %0, %1, %2, %0;" : "+l"(c) : "l"(a), "l"(b))

// ------------------------- device scratch (no allocs allowed) ---------------
__device__ int   g_cnt[NNODES];          // counts; self-zeroed by k_fill
__device__ int   g_rowptr[NNODES + 1];
__device__ int   g_col[NEDGES];
__device__ float g_dinv[NNODES];
__device__ int   g_bsums[NB_SCAN];
__device__ float g_bufA[(size_t)NNODES * 64];
__device__ float g_bufB[(size_t)NNODES * 64];
__device__ float g_buf128[(size_t)NNODES * 128];

// ------------------------------- CSR build ----------------------------------
__global__ void k_count(const int* __restrict__ dst) {
    int e = blockIdx.x * blockDim.x + threadIdx.x;
    if (e < NEDGES) atomicAdd(&g_cnt[dst[e]], 1);
}

__global__ void k_bsum() {
    __shared__ int s[256];
    int t = threadIdx.x;
    int base = blockIdx.x * 1024 + t * 4;
    int sum = 0;
#pragma unroll
    for (int i = 0; i < 4; i++) { int idx = base + i; if (idx < NNODES) sum += g_cnt[idx]; }
    s[t] = sum; __syncthreads();
    for (int off = 128; off > 0; off >>= 1) {
        if (t < off) s[t] += s[t + off];
        __syncthreads();
    }
    if (t == 0) g_bsums[blockIdx.x] = s[0];
}

// rowptr + dinv; computes its own block offset from raw g_bsums (no scan kernel)
__global__ void k_writeptr() {
    __shared__ int s[256];
    __shared__ int sb[NB_SCAN];
    __shared__ int s_off;
    int t = threadIdx.x;
    if (t < NB_SCAN) sb[t] = g_bsums[t];

    int base = blockIdx.x * 1024 + t * 4;
    int c[4]; int sum = 0;
#pragma unroll
    for (int i = 0; i < 4; i++) {
        int idx = base + i;
        c[i] = (idx < NNODES) ? g_cnt[idx] : 0;
        sum += c[i];
    }
    s[t] = sum; __syncthreads();

    if (t == 0) {
        int r = 0;
        for (int i = 0; i < (int)blockIdx.x; i++) r += sb[i];
        s_off = r;
    }
    // inclusive Hillis-Steele scan over thread sums
    for (int off = 1; off < 256; off <<= 1) {
        int v = (t >= off) ? s[t - off] : 0;
        __syncthreads();
        s[t] += v;
        __syncthreads();
    }
    int excl = s[t] - sum + s_off;
#pragma unroll
    for (int i = 0; i < 4; i++) {
        int idx = base + i;
        if (idx < NNODES) {
            g_rowptr[idx] = excl;
            g_dinv[idx] = rsqrtf((float)c[i] + 1.0f);
            excl += c[i];
        }
    }
    if (blockIdx.x == 0 && t == 0) g_rowptr[NNODES] = NEDGES;
}

// fill via atomicSub on counts -> counts end at 0 (ready for next launch)
__global__ void k_fill(const int* __restrict__ src, const int* __restrict__ dst) {
    int e = blockIdx.x * blockDim.x + threadIdx.x;
    if (e >= NEDGES) return;
    int d = dst[e];
    int pos = atomicSub(&g_cnt[d], 1) - 1;
    g_col[g_rowptr[d] + pos] = src[e];
}

// --------------------------------- GEMM -------------------------------------
// C[N x OUTtot] = A[N x IN] @ W[IN x OUTtot].
// 128x64 tile / block, 256 threads, 8x4 micro-tile using packed fp32x2 FMA.
// A is stored duplicated (a,a) in smem so inner loop is LDS.128 + FFMA2 only.
template <int IN, bool SCALE, bool BIAS, bool RELU>
__global__ __launch_bounds__(256) void k_gemm(
    const float* __restrict__ A, const float* __restrict__ W,
    const float* __restrict__ bias, float* __restrict__ C, int OUTtot)
{
    __shared__ float As[16][256];   // [k][2*row] duplicated pairs
    __shared__ float Ws[16][64];
    int t  = threadIdx.x;
    int tx = t & 15, ty = t >> 4;
    int row0 = blockIdx.x * 128;
    int bn0  = blockIdx.y * 64;

    unsigned long long acc[8][2];
#pragma unroll
    for (int i = 0; i < 8; i++) { acc[i][0] = 0ull; acc[i][1] = 0ull; }

    int lr  = t & 127;          // A-load row within tile
    int lk0 = (t >> 7) * 8;     // A-load k-octet
    int wk  = t >> 4;           // W-load k
    int wn  = (t & 15) * 4;     // W-load col quad

    for (int kk = 0; kk < IN; kk += 16) {
        float4 a0 = make_float4(0.f,0.f,0.f,0.f), a1 = a0;
        int gr = row0 + lr;
        if (gr < NNODES) {
            const float* ap = &A[(size_t)gr * IN + kk + lk0];
            a0 = *(const float4*)ap;
            a1 = *(const float4*)(ap + 4);
        }
        *(float2*)&As[lk0+0][2*lr] = make_float2(a0.x, a0.x);
        *(float2*)&As[lk0+1][2*lr] = make_float2(a0.y, a0.y);
        *(float2*)&As[lk0+2][2*lr] = make_float2(a0.z, a0.z);
        *(float2*)&As[lk0+3][2*lr] = make_float2(a0.w, a0.w);
        *(float2*)&As[lk0+4][2*lr] = make_float2(a1.x, a1.x);
        *(float2*)&As[lk0+5][2*lr] = make_float2(a1.y, a1.y);
        *(float2*)&As[lk0+6][2*lr] = make_float2(a1.z, a1.z);
        *(float2*)&As[lk0+7][2*lr] = make_float2(a1.w, a1.w);

        *(float4*)&Ws[wk][wn] =
            *(const float4*)&W[(size_t)(kk + wk) * OUTtot + bn0 + wn];
        __syncthreads();

#pragma unroll
        for (int k = 0; k < 16; k++) {
            ulonglong2 b2 = *(const ulonglong2*)&Ws[k][tx * 4];
            const float* ab = &As[k][16 * ty];
            ulonglong2 q0 = *(const ulonglong2*)(ab + 0);
            ulonglong2 q1 = *(const ulonglong2*)(ab + 4);
            ulonglong2 q2 = *(const ulonglong2*)(ab + 8);
            ulonglong2 q3 = *(const ulonglong2*)(ab + 12);
            FMA2(acc[0][0], q0.x, b2.x); FMA2(acc[0][1], q0.x, b2.y);
            FMA2(acc[1][0], q0.y, b2.x); FMA2(acc[1][1], q0.y, b2.y);
            FMA2(acc[2][0], q1.x, b2.x); FMA2(acc[2][1], q1.x, b2.y);
            FMA2(acc[3][0], q1.y, b2.x); FMA2(acc[3][1], q1.y, b2.y);
            FMA2(acc[4][0], q2.x, b2.x); FMA2(acc[4][1], q2.x, b2.y);
            FMA2(acc[5][0], q2.y, b2.x); FMA2(acc[5][1], q2.y, b2.y);
            FMA2(acc[6][0], q3.x, b2.x); FMA2(acc[6][1], q3.x, b2.y);
            FMA2(acc[7][0], q3.y, b2.x); FMA2(acc[7][1], q3.y, b2.y);
        }
        __syncthreads();
    }

    float4 bj = make_float4(0.f, 0.f, 0.f, 0.f);
    if (BIAS) bj = *(const float4*)&bias[bn0 + tx * 4];
#pragma unroll
    for (int r = 0; r < 8; r++) {
        int row = row0 + ty * 8 + r;
        if (row >= NNODES) continue;
        union { unsigned long long u; float2 f; } c0, c1;
        c0.u = acc[r][0]; c1.u = acc[r][1];
        float4 v = make_float4(c0.f.x + bj.x, c0.f.y + bj.y,
                               c1.f.x + bj.z, c1.f.y + bj.w);
        if (RELU) {
            v.x = fmaxf(v.x, 0.f); v.y = fmaxf(v.y, 0.f);
            v.z = fmaxf(v.z, 0.f); v.w = fmaxf(v.w, 0.f);
        }
        if (SCALE) {
            float di = g_dinv[row];
            v.x *= di; v.y *= di; v.z *= di; v.w *= di;
        }
        *(float4*)&C[(size_t)row * OUTtot + bn0 + tx * 4] = v;
    }
}

// ----------------------------- Aggregation -----------------------------------
// One warp per destination node, 64-dim features (2 floats / lane).
template <bool BIAS, bool RELU, bool POSTSCALE>
__global__ __launch_bounds__(256) void k_agg64(
    const float* __restrict__ U, const float* __restrict__ bias,
    float* __restrict__ Out)
{
    int warp = (blockIdx.x * blockDim.x + threadIdx.x) >> 5;
    int lane = threadIdx.x & 31;
    if (warp >= NNODES) return;
    int d = warp;

    float2 acc  = *(const float2*)&U[(size_t)d * 64 + 2 * lane];   // self loop
    float2 acc2 = make_float2(0.f, 0.f);

    int b = g_rowptr[d], e = g_rowptr[d + 1];
    int j = b;
    for (; j + 1 < e; j += 2) {
        int s0 = __ldg(&g_col[j]);
        int s1 = __ldg(&g_col[j + 1]);
        float2 v0 = *(const float2*)&U[(size_t)s0 * 64 + 2 * lane];
        float2 v1 = *(const float2*)&U[(size_t)s1 * 64 + 2 * lane];
        acc.x  += v0.x; acc.y  += v0.y;
        acc2.x += v1.x; acc2.y += v1.y;
    }
    if (j < e) {
        int s0 = __ldg(&g_col[j]);
        float2 v0 = *(const float2*)&U[(size_t)s0 * 64 + 2 * lane];
        acc.x += v0.x; acc.y += v0.y;
    }
    acc.x += acc2.x; acc.y += acc2.y;

    float di = g_dinv[d];
    float ox = acc.x * di, oy = acc.y * di;
    if (BIAS) { ox += bias[2 * lane]; oy += bias[2 * lane + 1]; }
    if (RELU) { ox = fmaxf(ox, 0.f); oy = fmaxf(oy, 0.f); }
    if (POSTSCALE) { ox *= di; oy *= di; }
    *(float2*)&Out[(size_t)d * 64 + 2 * lane] = make_float2(ox, oy);
}

// ------------------------------- launch --------------------------------------
extern "C" void kernel_launch(void* const* d_in, const int* in_sizes, int n_in,
                              void* d_out, int out_size)
{
    const float* x  = (const float*)d_in[0];
    const int*   ei = (const int*)d_in[1];
    const float* W1 = (const float*)d_in[2];
    const float* b1 = (const float*)d_in[3];
    const float* W2 = (const float*)d_in[4];
    const float* b2 = (const float*)d_in[5];
    const float* W3 = (const float*)d_in[6];
    const float* b3 = (const float*)d_in[7];
    float* out = (float*)d_out;

    const int* src = ei;
    const int* dst = ei + NEDGES;

    float *bufA, *bufB, *buf128;
    cudaGetSymbolAddress((void**)&bufA,   g_bufA);
    cudaGetSymbolAddress((void**)&bufB,   g_bufB);
    cudaGetSymbolAddress((void**)&buf128, g_buf128);

    const int EB = (NEDGES + 255) / 256;          // 6250
    const int GB = (NNODES + 127) / 128;          // 782 gemm row-tiles
    const int AB = (NNODES * 32 + 255) / 256;     // 12500 agg blocks (8 warps)

    // --- CSR build (shared by all 3 layers) ---
    k_count<<<EB, 256>>>(dst);
    k_bsum<<<NB_SCAN, 256>>>();
    k_writeptr<<<NB_SCAN, 256>>>();
    k_fill<<<EB, 256>>>(src, dst);

    // --- Layer 1: u1 = dinv*(x@W1); t = relu(dinv*S(u1)+b1)*dinv ---
    k_gemm<128, true, false, false><<<dim3(GB, 1), 256>>>(x, W1, nullptr, bufA, 64);
    k_agg64<true, true, true><<<AB, 256>>>(bufA, b1, bufB);

    // --- Layer 2: a2 = dinv*S(t); y2 = relu(a2@W2 + b2) ---
    k_agg64<false, false, false><<<AB, 256>>>(bufB, nullptr, bufA);
    k_gemm<64, false, true, true><<<dim3(GB, 2), 256>>>(bufA, W2, b2, buf128, 128);

    // --- Layer 3: u3 = dinv*(y2@W3); out = dinv*S(u3) + b3 ---
    k_gemm<128, true, false, false><<<dim3(GB, 1), 256>>>(buf128, W3, nullptr, bufA, 64);
    k_agg64<true, false, false><<<AB, 256>>>(bufA, b3, out);

    (void)in_sizes; (void)n_in; (void)out_size;
}

// round 4
// speedup vs baseline: 1.1278x; 1.1278x over previous
#include <cuda_runtime.h>
#include <math.h>
#include <stdint.h>

#define NNODES 100000
#define NEDGES 1600000
#define NB_SCAN 98   /* ceil(NNODES/1024) */

// ------------------------- device scratch (no allocs allowed) ---------------
__device__ int   g_cnt[NNODES];          // counts; self-zeroed by k_fill
__device__ int   g_rowptr[NNODES + 1];
__device__ int   g_col[NEDGES];
__device__ float g_dinv[NNODES];
__device__ int   g_bsums[NB_SCAN];
__device__ float g_bufA[(size_t)NNODES * 64];
__device__ float g_bufB[(size_t)NNODES * 64];
__device__ float g_buf128[(size_t)NNODES * 128];
// tf32-split weights, K-major [n][k]: L1 @0 (64x128), L2 @8192 (128x64), L3 @16384
__device__ float g_Whi[24576];
__device__ float g_Wlo[24576];

// ----------------------------- tf32 helpers ---------------------------------
__device__ __forceinline__ uint32_t f2tf32(float x) {
    uint32_t r;
    asm("cvt.rna.tf32.f32 %0, %1;" : "=r"(r) : "f"(x));
    return r;
}
__device__ __forceinline__ void mma_tf32(float c[4],
    uint32_t a0, uint32_t a1, uint32_t a2, uint32_t a3,
    uint32_t b0, uint32_t b1)
{
    asm volatile("mma.sync.aligned.m16n8k8.row.col.f32.tf32.tf32.f32 "
        "{%0,%1,%2,%3}, {%4,%5,%6,%7}, {%8,%9}, {%0,%1,%2,%3};"
        : "+f"(c[0]), "+f"(c[1]), "+f"(c[2]), "+f"(c[3])
        : "r"(a0), "r"(a1), "r"(a2), "r"(a3), "r"(b0), "r"(b1));
}

// ------------------------------- CSR build ----------------------------------
__global__ void k_count(const int* __restrict__ dst) {
    int e = blockIdx.x * blockDim.x + threadIdx.x;
    if (e < NEDGES) atomicAdd(&g_cnt[dst[e]], 1);
}

__global__ void k_bsum() {
    __shared__ int s[256];
    int t = threadIdx.x;
    int base = blockIdx.x * 1024 + t * 4;
    int sum = 0;
#pragma unroll
    for (int i = 0; i < 4; i++) { int idx = base + i; if (idx < NNODES) sum += g_cnt[idx]; }
    s[t] = sum; __syncthreads();
    for (int off = 128; off > 0; off >>= 1) {
        if (t < off) s[t] += s[t + off];
        __syncthreads();
    }
    if (t == 0) g_bsums[blockIdx.x] = s[0];
}

__global__ void k_writeptr() {
    __shared__ int s[256];
    __shared__ int sb[NB_SCAN];
    __shared__ int s_off;
    int t = threadIdx.x;
    if (t < NB_SCAN) sb[t] = g_bsums[t];

    int base = blockIdx.x * 1024 + t * 4;
    int c[4]; int sum = 0;
#pragma unroll
    for (int i = 0; i < 4; i++) {
        int idx = base + i;
        c[i] = (idx < NNODES) ? g_cnt[idx] : 0;
        sum += c[i];
    }
    s[t] = sum; __syncthreads();
    if (t == 0) {
        int r = 0;
        for (int i = 0; i < (int)blockIdx.x; i++) r += sb[i];
        s_off = r;
    }
    for (int off = 1; off < 256; off <<= 1) {
        int v = (t >= off) ? s[t - off] : 0;
        __syncthreads();
        s[t] += v;
        __syncthreads();
    }
    int excl = s[t] - sum + s_off;
#pragma unroll
    for (int i = 0; i < 4; i++) {
        int idx = base + i;
        if (idx < NNODES) {
            g_rowptr[idx] = excl;
            g_dinv[idx] = rsqrtf((float)c[i] + 1.0f);
            excl += c[i];
        }
    }
    if (blockIdx.x == 0 && t == 0) g_rowptr[NNODES] = NEDGES;
}

__global__ void k_fill(const int* __restrict__ src, const int* __restrict__ dst) {
    int e = blockIdx.x * blockDim.x + threadIdx.x;
    if (e >= NEDGES) return;
    int d = dst[e];
    int pos = atomicSub(&g_cnt[d], 1) - 1;
    g_col[g_rowptr[d] + pos] = src[e];
}

// --------------------- weight split (fp32 -> tf32 hi/lo, K-major) -----------
__global__ void k_wsplit(const float* __restrict__ W1, const float* __restrict__ W2,
                         const float* __restrict__ W3) {
    int i = blockIdx.x * 256 + threadIdx.x;
    if (i >= 24576) return;
    const float* W; int IN, OUT, idx;
    if (i < 8192)       { W = W1; IN = 128; OUT = 64;  idx = i; }
    else if (i < 16384) { W = W2; IN = 64;  OUT = 128; idx = i - 8192; }
    else                { W = W3; IN = 128; OUT = 64;  idx = i - 16384; }
    int n = idx / IN, k = idx % IN;
    float x = W[k * OUT + n];
    uint32_t hi = f2tf32(x);
    float hif = __uint_as_float(hi);
    g_Whi[i] = hif;
    g_Wlo[i] = __uint_as_float(f2tf32(x - hif));
}

// --------------------------- TF32 mma GEMM ----------------------------------
// C[N x OUT] = A[N x IN] @ W; W pre-split hi/lo, K-major [OUT][IN].
// CTA: 128 rows, 256 thr (8 warps x 16-row slabs). Full K in smem.
// Packed-pair smem layout: element (r, kk*8 + j + 4*p) at [r][kk*8 + j*2 + p],
// row stride padded to IN+8 floats -> conflict-free LDS.64 fragments.
template <int IN, int OUT, bool SCALE, bool BIAS, bool RELU>
__global__ __launch_bounds__(256) void k_mma(
    const float* __restrict__ A,
    const float* __restrict__ Whi, const float* __restrict__ Wlo,
    const float* __restrict__ bias, float* __restrict__ C)
{
    extern __shared__ float sm[];
    constexpr int AS = IN + 8;
    constexpr int A_FLOATS = 128 * AS;
    constexpr int B_FLOATS = OUT * AS;
    constexpr int NT = OUT / 8;
    constexpr int KK = IN / 8;
    float* sA  = sm;
    float* sBh = sm + A_FLOATS;
    float* sBl = sBh + B_FLOATS;

    int t = threadIdx.x;
    int row0 = blockIdx.x * 128;

    // --- stage A (fp32) ---
#pragma unroll
    for (int i = 0; i < (128 * IN / 4) / 256; i++) {
        int idx = t + i * 256;
        int row = idx / (IN / 4);
        int k0  = (idx % (IN / 4)) * 4;
        float4 v = make_float4(0.f, 0.f, 0.f, 0.f);
        if (row0 + row < NNODES)
            v = *(const float4*)&A[(size_t)(row0 + row) * IN + k0];
        float* d = &sA[row * AS + (k0 >> 3) * 8 + ((k0 >> 2) & 1)];
        d[0] = v.x; d[2] = v.y; d[4] = v.z; d[6] = v.w;
    }
    // --- stage B hi/lo ---
#pragma unroll
    for (int i = 0; i < (OUT * IN / 4) / 256; i++) {
        int idx = t + i * 256;
        int n  = idx / (IN / 4);
        int k0 = (idx % (IN / 4)) * 4;
        float4 h = *(const float4*)&Whi[(size_t)n * IN + k0];
        float4 l = *(const float4*)&Wlo[(size_t)n * IN + k0];
        int off = n * AS + (k0 >> 3) * 8 + ((k0 >> 2) & 1);
        sBh[off] = h.x; sBh[off + 2] = h.y; sBh[off + 4] = h.z; sBh[off + 6] = h.w;
        sBl[off] = l.x; sBl[off + 2] = l.y; sBl[off + 4] = l.z; sBl[off + 6] = l.w;
    }
    __syncthreads();

    int lane = t & 31, warp = t >> 5;
    int g = lane >> 2, j = lane & 3;
    int arow = warp * 16 + g;

    const float* pA0 = &sA[arow * AS + j * 2];
    const float* pA1 = &sA[(arow + 8) * AS + j * 2];
    const float* pBh = &sBh[g * AS + j * 2];   // g doubles as n-group (lane>>2)
    const float* pBl = &sBl[g * AS + j * 2];

    float c[NT][4];
#pragma unroll
    for (int n = 0; n < NT; n++) { c[n][0] = c[n][1] = c[n][2] = c[n][3] = 0.f; }

#pragma unroll
    for (int kk = 0; kk < KK; kk++) {
        float2 a02 = *(const float2*)(pA0 + kk * 8);
        float2 a13 = *(const float2*)(pA1 + kk * 8);
        uint32_t ah0 = f2tf32(a02.x), ah2 = f2tf32(a02.y);
        uint32_t ah1 = f2tf32(a13.x), ah3 = f2tf32(a13.y);
        uint32_t al0 = f2tf32(a02.x - __uint_as_float(ah0));
        uint32_t al2 = f2tf32(a02.y - __uint_as_float(ah2));
        uint32_t al1 = f2tf32(a13.x - __uint_as_float(ah1));
        uint32_t al3 = f2tf32(a13.y - __uint_as_float(ah3));
#pragma unroll
        for (int n = 0; n < NT; n++) {
            uint2 bh = *(const uint2*)(pBh + n * 8 * AS + kk * 8);
            uint2 bl = *(const uint2*)(pBl + n * 8 * AS + kk * 8);
            mma_tf32(c[n], ah0, ah1, ah2, ah3, bh.x, bh.y);
            mma_tf32(c[n], ah0, ah1, ah2, ah3, bl.x, bl.y);
            mma_tf32(c[n], al0, al1, al2, al3, bh.x, bh.y);
        }
    }

    // --- epilogue: bias/relu/dinv + STG.64 ---
    int r0 = row0 + arow, r1 = r0 + 8;
    float d0 = 1.f, d1 = 1.f;
    if (SCALE) {
        if (r0 < NNODES) d0 = g_dinv[r0];
        if (r1 < NNODES) d1 = g_dinv[r1];
    }
#pragma unroll
    for (int n = 0; n < NT; n++) {
        int col = n * 8 + 2 * j;
        float b0 = 0.f, b1 = 0.f;
        if (BIAS) { b0 = __ldg(&bias[col]); b1 = __ldg(&bias[col + 1]); }
        float v0 = c[n][0] + b0, v1 = c[n][1] + b1;
        float v2 = c[n][2] + b0, v3 = c[n][3] + b1;
        if (RELU) {
            v0 = fmaxf(v0, 0.f); v1 = fmaxf(v1, 0.f);
            v2 = fmaxf(v2, 0.f); v3 = fmaxf(v3, 0.f);
        }
        if (SCALE) { v0 *= d0; v1 *= d0; v2 *= d1; v3 *= d1; }
        if (r0 < NNODES) *(float2*)&C[(size_t)r0 * OUT + col] = make_float2(v0, v1);
        if (r1 < NNODES) *(float2*)&C[(size_t)r1 * OUT + col] = make_float2(v2, v3);
    }
}

// ----------------------------- Aggregation -----------------------------------
template <bool BIAS, bool RELU, bool POSTSCALE>
__global__ __launch_bounds__(256) void k_agg64(
    const float* __restrict__ U, const float* __restrict__ bias,
    float* __restrict__ Out)
{
    int warp = (blockIdx.x * blockDim.x + threadIdx.x) >> 5;
    int lane = threadIdx.x & 31;
    if (warp >= NNODES) return;
    int d = warp;

    float2 acc  = *(const float2*)&U[(size_t)d * 64 + 2 * lane];   // self loop
    float2 acc2 = make_float2(0.f, 0.f);

    int b = g_rowptr[d], e = g_rowptr[d + 1];
    int j = b;
    for (; j + 1 < e; j += 2) {
        int s0 = __ldg(&g_col[j]);
        int s1 = __ldg(&g_col[j + 1]);
        float2 v0 = *(const float2*)&U[(size_t)s0 * 64 + 2 * lane];
        float2 v1 = *(const float2*)&U[(size_t)s1 * 64 + 2 * lane];
        acc.x  += v0.x; acc.y  += v0.y;
        acc2.x += v1.x; acc2.y += v1.y;
    }
    if (j < e) {
        int s0 = __ldg(&g_col[j]);
        float2 v0 = *(const float2*)&U[(size_t)s0 * 64 + 2 * lane];
        acc.x += v0.x; acc.y += v0.y;
    }
    acc.x += acc2.x; acc.y += acc2.y;

    float di = g_dinv[d];
    float ox = acc.x * di, oy = acc.y * di;
    if (BIAS) { ox += bias[2 * lane]; oy += bias[2 * lane + 1]; }
    if (RELU) { ox = fmaxf(ox, 0.f); oy = fmaxf(oy, 0.f); }
    if (POSTSCALE) { ox *= di; oy *= di; }
    *(float2*)&Out[(size_t)d * 64 + 2 * lane] = make_float2(ox, oy);
}

// ------------------------------- launch --------------------------------------
extern "C" void kernel_launch(void* const* d_in, const int* in_sizes, int n_in,
                              void* d_out, int out_size)
{
    const float* x  = (const float*)d_in[0];
    const int*   ei = (const int*)d_in[1];
    const float* W1 = (const float*)d_in[2];
    const float* b1 = (const float*)d_in[3];
    const float* W2 = (const float*)d_in[4];
    const float* b2 = (const float*)d_in[5];
    const float* W3 = (const float*)d_in[6];
    const float* b3 = (const float*)d_in[7];
    float* out = (float*)d_out;

    const int* src = ei;
    const int* dst = ei + NEDGES;

    float *bufA, *bufB, *buf128, *whi, *wlo;
    cudaGetSymbolAddress((void**)&bufA,   g_bufA);
    cudaGetSymbolAddress((void**)&bufB,   g_bufB);
    cudaGetSymbolAddress((void**)&buf128, g_buf128);
    cudaGetSymbolAddress((void**)&whi,    g_Whi);
    cudaGetSymbolAddress((void**)&wlo,    g_Wlo);

    const int EB = (NEDGES + 255) / 256;
    const int GB = (NNODES + 127) / 128;          // 782 GEMM tiles
    const int AB = (NNODES * 32 + 255) / 256;     // agg blocks

    // smem: L1/L3: (128*136 + 2*64*136)*4 = 139264 ; L2: (128*72 + 2*128*72)*4 = 110592
    const int SM1 = (128 * 136 + 2 * 64 * 136) * 4;
    const int SM2 = (128 * 72 + 2 * 128 * 72) * 4;
    cudaFuncSetAttribute((const void*)k_mma<128, 64, true, false, false>,
                         cudaFuncAttributeMaxDynamicSharedMemorySize, SM1);
    cudaFuncSetAttribute((const void*)k_mma<64, 128, false, true, true>,
                         cudaFuncAttributeMaxDynamicSharedMemorySize, SM2);

    // --- prep: weight split + CSR build ---
    k_wsplit<<<96, 256>>>(W1, W2, W3);
    k_count<<<EB, 256>>>(dst);
    k_bsum<<<NB_SCAN, 256>>>();
    k_writeptr<<<NB_SCAN, 256>>>();
    k_fill<<<EB, 256>>>(src, dst);

    // --- Layer 1: u1 = dinv*(x@W1); t = relu(dinv*S(u1)+b1)*dinv ---
    k_mma<128, 64, true, false, false><<<GB, 256, SM1>>>(x, whi, wlo, nullptr, bufA);
    k_agg64<true, true, true><<<AB, 256>>>(bufA, b1, bufB);

    // --- Layer 2: a2 = dinv*S(t); y2 = relu(a2@W2 + b2) ---
    k_agg64<false, false, false><<<AB, 256>>>(bufB, nullptr, bufA);
    k_mma<64, 128, false, true, true><<<GB, 256, SM2>>>(bufA, whi + 8192, wlo + 8192, b2, buf128);

    // --- Layer 3: u3 = dinv*(y2@W3); out = dinv*S(u3) + b3 ---
    k_mma<128, 64, true, false, false><<<GB, 256, SM1>>>(buf128, whi + 16384, wlo + 16384, nullptr, bufA);
    k_agg64<true, false, false><<<AB, 256>>>(bufA, b3, out);

    (void)in_sizes; (void)n_in; (void)out_size;
}

// round 5
// speedup vs baseline: 1.1402x; 1.0110x over previous
#include <cuda_runtime.h>
#include <math.h>
#include <stdint.h>

#define NNODES 100000
#define NEDGES 1600000
#define NB_SCAN 98   /* ceil(NNODES/1024) */

// ------------------------- device scratch (no allocs allowed) ---------------
__device__ int   g_cnt[NNODES];          // counts; self-zeroed by k_fill
__device__ int   g_rowptr[NNODES + 1];
__device__ int   g_col[NEDGES];
__device__ float g_dinv[NNODES];
__device__ int   g_bsums[NB_SCAN];
__device__ float g_bufA[(size_t)NNODES * 64];
__device__ float g_bufB[(size_t)NNODES * 64];
__device__ float g_buf128[(size_t)NNODES * 128];
// tf32-split weights, K-major [n][k]: L1 @0 (64x128), L2 @8192 (128x64), L3 @16384
__device__ float g_Whi[24576];
__device__ float g_Wlo[24576];

// ----------------------------- tf32 helpers ---------------------------------
__device__ __forceinline__ uint32_t f2tf32(float x) {
    uint32_t r;
    asm("cvt.rna.tf32.f32 %0, %1;" : "=r"(r) : "f"(x));
    return r;
}
__device__ __forceinline__ void mma_tf32(float c[4],
    uint32_t a0, uint32_t a1, uint32_t a2, uint32_t a3,
    uint32_t b0, uint32_t b1)
{
    asm volatile("mma.sync.aligned.m16n8k8.row.col.f32.tf32.tf32.f32 "
        "{%0,%1,%2,%3}, {%4,%5,%6,%7}, {%8,%9}, {%0,%1,%2,%3};"
        : "+f"(c[0]), "+f"(c[1]), "+f"(c[2]), "+f"(c[3])
        : "r"(a0), "r"(a1), "r"(a2), "r"(a3), "r"(b0), "r"(b1));
}

// ------------------------------- CSR build ----------------------------------
__global__ void k_count(const int* __restrict__ dst) {
    int e = blockIdx.x * blockDim.x + threadIdx.x;
    if (e < NEDGES) atomicAdd(&g_cnt[dst[e]], 1);
}

__global__ void k_bsum() {
    __shared__ int s[256];
    int t = threadIdx.x;
    int base = blockIdx.x * 1024 + t * 4;
    int sum = 0;
#pragma unroll
    for (int i = 0; i < 4; i++) { int idx = base + i; if (idx < NNODES) sum += g_cnt[idx]; }
    s[t] = sum; __syncthreads();
    for (int off = 128; off > 0; off >>= 1) {
        if (t < off) s[t] += s[t + off];
        __syncthreads();
    }
    if (t == 0) g_bsums[blockIdx.x] = s[0];
}

__global__ void k_writeptr() {
    __shared__ int s[256];
    __shared__ int sb[NB_SCAN];
    __shared__ int s_off;
    int t = threadIdx.x;
    if (t < NB_SCAN) sb[t] = g_bsums[t];

    int base = blockIdx.x * 1024 + t * 4;
    int c[4]; int sum = 0;
#pragma unroll
    for (int i = 0; i < 4; i++) {
        int idx = base + i;
        c[i] = (idx < NNODES) ? g_cnt[idx] : 0;
        sum += c[i];
    }
    s[t] = sum; __syncthreads();
    if (t == 0) {
        int r = 0;
        for (int i = 0; i < (int)blockIdx.x; i++) r += sb[i];
        s_off = r;
    }
    for (int off = 1; off < 256; off <<= 1) {
        int v = (t >= off) ? s[t - off] : 0;
        __syncthreads();
        s[t] += v;
        __syncthreads();
    }
    int excl = s[t] - sum + s_off;
#pragma unroll
    for (int i = 0; i < 4; i++) {
        int idx = base + i;
        if (idx < NNODES) {
            g_rowptr[idx] = excl;
            g_dinv[idx] = rsqrtf((float)c[i] + 1.0f);
            excl += c[i];
        }
    }
    if (blockIdx.x == 0 && t == 0) g_rowptr[NNODES] = NEDGES;
}

__global__ void k_fill(const int* __restrict__ src, const int* __restrict__ dst) {
    int e = blockIdx.x * blockDim.x + threadIdx.x;
    if (e >= NEDGES) return;
    int d = dst[e];
    int pos = atomicSub(&g_cnt[d], 1) - 1;
    g_col[g_rowptr[d] + pos] = src[e];
}

// --------------------- weight split (fp32 -> tf32 hi/lo, K-major) -----------
__global__ void k_wsplit(const float* __restrict__ W1, const float* __restrict__ W2,
                         const float* __restrict__ W3) {
    int i = blockIdx.x * 256 + threadIdx.x;
    if (i >= 24576) return;
    const float* W; int IN, OUT, idx;
    if (i < 8192)       { W = W1; IN = 128; OUT = 64;  idx = i; }
    else if (i < 16384) { W = W2; IN = 64;  OUT = 128; idx = i - 8192; }
    else                { W = W3; IN = 128; OUT = 64;  idx = i - 16384; }
    int n = idx / IN, k = idx % IN;
    float x = W[k * OUT + n];
    uint32_t hi = f2tf32(x);
    float hif = __uint_as_float(hi);
    g_Whi[i] = hif;
    g_Wlo[i] = __uint_as_float(f2tf32(x - hif));
}

// --------------------------- TF32 mma GEMM ----------------------------------
// C[N x OUT] = A[N x IN] @ W; W pre-split hi/lo, K-major [OUT][IN].
// CTA: 128 rows, 256 thr (8 warps x 16-row slabs). A loaded directly from
// global (rows are warp-exclusive; features are L2-resident). Only B in smem,
// packed-pair layout + pad so LDS.64 fragments are near-conflict-free.
template <int IN, int OUT, bool SCALE, bool BIAS, bool RELU>
__global__ __launch_bounds__(256) void k_mma(
    const float* __restrict__ A,
    const float* __restrict__ Whi, const float* __restrict__ Wlo,
    const float* __restrict__ bias, float* __restrict__ C)
{
    extern __shared__ float sm[];
    constexpr int AS = IN + 8;
    constexpr int B_FLOATS = OUT * AS;
    constexpr int NT = OUT / 8;
    constexpr int KK = IN / 8;
    float* sBh = sm;
    float* sBl = sm + B_FLOATS;

    int t = threadIdx.x;
    int row0 = blockIdx.x * 128;

    // --- stage B hi/lo (packed-pair: col kk*8 + j + 4p -> [kk*8 + 2j + p]) ---
#pragma unroll
    for (int i = 0; i < (OUT * IN / 4) / 256; i++) {
        int idx = t + i * 256;
        int n  = idx / (IN / 4);
        int k0 = (idx % (IN / 4)) * 4;
        float4 h = *(const float4*)&Whi[(size_t)n * IN + k0];
        float4 l = *(const float4*)&Wlo[(size_t)n * IN + k0];
        int off = n * AS + (k0 >> 3) * 8 + ((k0 >> 2) & 1);
        sBh[off] = h.x; sBh[off + 2] = h.y; sBh[off + 4] = h.z; sBh[off + 6] = h.w;
        sBl[off] = l.x; sBl[off + 2] = l.y; sBl[off + 4] = l.z; sBl[off + 6] = l.w;
    }
    __syncthreads();

    int lane = t & 31, warp = t >> 5;
    int g = lane >> 2, j = lane & 3;
    int arow = warp * 16 + g;

    int r0 = row0 + arow, r1 = r0 + 8;
    // clamp for safe loads; stores are guarded below
    const float* a0p = &A[(size_t)(r0 < NNODES ? r0 : NNODES - 1) * IN + j];
    const float* a1p = &A[(size_t)(r1 < NNODES ? r1 : NNODES - 1) * IN + j];
    const float* pBh = &sBh[g * AS + j * 2];
    const float* pBl = &sBl[g * AS + j * 2];

    float c[NT][4];
#pragma unroll
    for (int n = 0; n < NT; n++) { c[n][0] = c[n][1] = c[n][2] = c[n][3] = 0.f; }

#pragma unroll 4
    for (int kk = 0; kk < KK; kk++) {
        float a0x = __ldg(a0p + kk * 8);
        float a0y = __ldg(a0p + kk * 8 + 4);
        float a1x = __ldg(a1p + kk * 8);
        float a1y = __ldg(a1p + kk * 8 + 4);
        uint32_t ah0 = f2tf32(a0x), ah2 = f2tf32(a0y);
        uint32_t ah1 = f2tf32(a1x), ah3 = f2tf32(a1y);
        uint32_t al0 = f2tf32(a0x - __uint_as_float(ah0));
        uint32_t al2 = f2tf32(a0y - __uint_as_float(ah2));
        uint32_t al1 = f2tf32(a1x - __uint_as_float(ah1));
        uint32_t al3 = f2tf32(a1y - __uint_as_float(ah3));
#pragma unroll
        for (int n = 0; n < NT; n++) {
            uint2 bh = *(const uint2*)(pBh + n * 8 * AS + kk * 8);
            uint2 bl = *(const uint2*)(pBl + n * 8 * AS + kk * 8);
            mma_tf32(c[n], ah0, ah1, ah2, ah3, bh.x, bh.y);
            mma_tf32(c[n], ah0, ah1, ah2, ah3, bl.x, bl.y);
            mma_tf32(c[n], al0, al1, al2, al3, bh.x, bh.y);
        }
    }

    // --- epilogue: bias/relu/dinv + STG.64 ---
    float d0 = 1.f, d1 = 1.f;
    if (SCALE) {
        if (r0 < NNODES) d0 = g_dinv[r0];
        if (r1 < NNODES) d1 = g_dinv[r1];
    }
#pragma unroll
    for (int n = 0; n < NT; n++) {
        int col = n * 8 + 2 * j;
        float b0 = 0.f, b1 = 0.f;
        if (BIAS) { b0 = __ldg(&bias[col]); b1 = __ldg(&bias[col + 1]); }
        float v0 = c[n][0] + b0, v1 = c[n][1] + b1;
        float v2 = c[n][2] + b0, v3 = c[n][3] + b1;
        if (RELU) {
            v0 = fmaxf(v0, 0.f); v1 = fmaxf(v1, 0.f);
            v2 = fmaxf(v2, 0.f); v3 = fmaxf(v3, 0.f);
        }
        if (SCALE) { v0 *= d0; v1 *= d0; v2 *= d1; v3 *= d1; }
        if (r0 < NNODES) *(float2*)&C[(size_t)r0 * OUT + col] = make_float2(v0, v1);
        if (r1 < NNODES) *(float2*)&C[(size_t)r1 * OUT + col] = make_float2(v2, v3);
    }
}

// ----------------------------- Aggregation -----------------------------------
// One warp per destination node, 64-dim features (2 floats / lane).
// EDGESCALE: multiply each gathered row by dinv[s] (and self by dinv[d]).
template <bool EDGESCALE, bool BIAS, bool RELU, bool POSTSCALE>
__global__ __launch_bounds__(256) void k_agg64(
    const float* __restrict__ U, const float* __restrict__ bias,
    float* __restrict__ Out)
{
    int warp = (blockIdx.x * blockDim.x + threadIdx.x) >> 5;
    int lane = threadIdx.x & 31;
    if (warp >= NNODES) return;
    int d = warp;

    float di = g_dinv[d];
    float selfs = EDGESCALE ? di : 1.0f;
    float2 u = *(const float2*)&U[(size_t)d * 64 + 2 * lane];
    float2 acc  = make_float2(u.x * selfs, u.y * selfs);   // self loop
    float2 acc2 = make_float2(0.f, 0.f);

    int b = g_rowptr[d], e = g_rowptr[d + 1];
    int j = b;
    for (; j + 1 < e; j += 2) {
        int s0 = __ldg(&g_col[j]);
        int s1 = __ldg(&g_col[j + 1]);
        float2 v0 = *(const float2*)&U[(size_t)s0 * 64 + 2 * lane];
        float2 v1 = *(const float2*)&U[(size_t)s1 * 64 + 2 * lane];
        float w0 = EDGESCALE ? __ldg(&g_dinv[s0]) : 1.0f;
        float w1 = EDGESCALE ? __ldg(&g_dinv[s1]) : 1.0f;
        acc.x  = fmaf(v0.x, w0, acc.x);  acc.y  = fmaf(v0.y, w0, acc.y);
        acc2.x = fmaf(v1.x, w1, acc2.x); acc2.y = fmaf(v1.y, w1, acc2.y);
    }
    if (j < e) {
        int s0 = __ldg(&g_col[j]);
        float2 v0 = *(const float2*)&U[(size_t)s0 * 64 + 2 * lane];
        float w0 = EDGESCALE ? __ldg(&g_dinv[s0]) : 1.0f;
        acc.x = fmaf(v0.x, w0, acc.x); acc.y = fmaf(v0.y, w0, acc.y);
    }
    acc.x += acc2.x; acc.y += acc2.y;

    float ox = acc.x * di, oy = acc.y * di;
    if (BIAS) { ox += bias[2 * lane]; oy += bias[2 * lane + 1]; }
    if (RELU) { ox = fmaxf(ox, 0.f); oy = fmaxf(oy, 0.f); }
    if (POSTSCALE) { ox *= di; oy *= di; }
    *(float2*)&Out[(size_t)d * 64 + 2 * lane] = make_float2(ox, oy);
}

// ------------------------------- launch --------------------------------------
extern "C" void kernel_launch(void* const* d_in, const int* in_sizes, int n_in,
                              void* d_out, int out_size)
{
    const float* x  = (const float*)d_in[0];
    const int*   ei = (const int*)d_in[1];
    const float* W1 = (const float*)d_in[2];
    const float* b1 = (const float*)d_in[3];
    const float* W2 = (const float*)d_in[4];
    const float* b2 = (const float*)d_in[5];
    const float* W3 = (const float*)d_in[6];
    const float* b3 = (const float*)d_in[7];
    float* out = (float*)d_out;

    const int* src = ei;
    const int* dst = ei + NEDGES;

    float *bufA, *bufB, *buf128, *whi, *wlo;
    cudaGetSymbolAddress((void**)&bufA,   g_bufA);
    cudaGetSymbolAddress((void**)&bufB,   g_bufB);
    cudaGetSymbolAddress((void**)&buf128, g_buf128);
    cudaGetSymbolAddress((void**)&whi,    g_Whi);
    cudaGetSymbolAddress((void**)&wlo,    g_Wlo);

    const int EB = (NEDGES + 255) / 256;
    const int GB = (NNODES + 127) / 128;          // 782 GEMM tiles
    const int AB = (NNODES * 32 + 255) / 256;     // agg blocks

    // smem (B only): L1/L3: 2*64*136*4 = 69632 ; L2: 2*128*72*4 = 73728
    const int SM1 = 2 * 64 * 136 * 4;
    const int SM2 = 2 * 128 * 72 * 4;
    cudaFuncSetAttribute((const void*)k_mma<128, 64, false, false, false>,
                         cudaFuncAttributeMaxDynamicSharedMemorySize, SM1);
    cudaFuncSetAttribute((const void*)k_mma<64, 128, false, true, true>,
                         cudaFuncAttributeMaxDynamicSharedMemorySize, SM2);
    cudaFuncSetAttribute((const void*)k_mma<128, 64, true, false, false>,
                         cudaFuncAttributeMaxDynamicSharedMemorySize, SM1);

    // --- prep + CSR; GEMM1 moved early (needs only wsplit, no dinv) ---
    k_wsplit<<<96, 256>>>(W1, W2, W3);                                   // 1
    k_count<<<EB, 256>>>(dst);                                           // 2
    k_bsum<<<NB_SCAN, 256>>>();                                          // 3
    k_mma<128, 64, false, false, false><<<GB, 256, SM1>>>(x, whi, wlo, nullptr, bufA); // 4 (profiled)
    k_writeptr<<<NB_SCAN, 256>>>();                                      // 5
    k_fill<<<EB, 256>>>(src, dst);                                       // 6

    // --- Layer 1 agg: t = relu(dinv*S(dinv_s*u1)+b1); out *dinv (prescale) ---
    k_agg64<true, true, true, true><<<AB, 256>>>(bufA, b1, bufB);        // 7

    // --- Layer 2: a2 = dinv*S(t*dinv); y2 = relu(a2@W2 + b2) ---
    k_agg64<false, false, false, false><<<AB, 256>>>(bufB, nullptr, bufA);             // 8
    k_mma<64, 128, false, true, true><<<GB, 256, SM2>>>(bufA, whi + 8192, wlo + 8192, b2, buf128); // 9

    // --- Layer 3: u3 = dinv*(y2@W3); out = dinv*S(u3) + b3 ---
    k_mma<128, 64, true, false, false><<<GB, 256, SM1>>>(buf128, whi + 16384, wlo + 16384, nullptr, bufA); // 10
    k_agg64<false, true, false, false><<<AB, 256>>>(bufA, b3, out);      // 11

    (void)in_sizes; (void)n_in; (void)out_size;
}

// round 6
// speedup vs baseline: 1.1557x; 1.0137x over previous
#include <cuda_runtime.h>
#include <math.h>
#include <stdint.h>

#define NNODES 100000
#define NEDGES 1600000
#define NB_SCAN 98   /* ceil(NNODES/1024) */

// ------------------------- device scratch (no allocs allowed) ---------------
__device__ int   g_cnt[NNODES];          // counts; self-zeroed by k_fill
__device__ int   g_rowptr[NNODES + 1];
__device__ int   g_col[NEDGES];
__device__ float g_dinv[NNODES];
__device__ int   g_bsums[NB_SCAN];
__device__ float g_bufA[(size_t)NNODES * 64];
__device__ float g_bufB[(size_t)NNODES * 64];
__device__ float g_buf128[(size_t)NNODES * 128];
// tf32-split weights, K-major [n][k]: L1 @0 (64x128), L2 @8192 (128x64), L3 @16384
__device__ float g_Whi[24576];
__device__ float g_Wlo[24576];

// ----------------------------- tf32 helpers ---------------------------------
__device__ __forceinline__ uint32_t f2tf32(float x) {
    uint32_t r;
    asm("cvt.rna.tf32.f32 %0, %1;" : "=r"(r) : "f"(x));
    return r;
}
__device__ __forceinline__ void mma_tf32(float c[4],
    uint32_t a0, uint32_t a1, uint32_t a2, uint32_t a3,
    uint32_t b0, uint32_t b1)
{
    asm volatile("mma.sync.aligned.m16n8k8.row.col.f32.tf32.tf32.f32 "
        "{%0,%1,%2,%3}, {%4,%5,%6,%7}, {%8,%9}, {%0,%1,%2,%3};"
        : "+f"(c[0]), "+f"(c[1]), "+f"(c[2]), "+f"(c[3])
        : "r"(a0), "r"(a1), "r"(a2), "r"(a3), "r"(b0), "r"(b1));
}

// ------------------------------- CSR build ----------------------------------
__global__ void k_count(const int* __restrict__ dst) {
    int e = blockIdx.x * blockDim.x + threadIdx.x;
    if (e < NEDGES) atomicAdd(&g_cnt[dst[e]], 1);
}

__global__ void k_bsum() {
    __shared__ int s[256];
    int t = threadIdx.x;
    int base = blockIdx.x * 1024 + t * 4;
    int sum = 0;
#pragma unroll
    for (int i = 0; i < 4; i++) { int idx = base + i; if (idx < NNODES) sum += g_cnt[idx]; }
    s[t] = sum; __syncthreads();
    for (int off = 128; off > 0; off >>= 1) {
        if (t < off) s[t] += s[t + off];
        __syncthreads();
    }
    if (t == 0) g_bsums[blockIdx.x] = s[0];
}

__global__ void k_writeptr() {
    __shared__ int s[256];
    __shared__ int sb[NB_SCAN];
    __shared__ int s_off;
    int t = threadIdx.x;
    if (t < NB_SCAN) sb[t] = g_bsums[t];

    int base = blockIdx.x * 1024 + t * 4;
    int c[4]; int sum = 0;
#pragma unroll
    for (int i = 0; i < 4; i++) {
        int idx = base + i;
        c[i] = (idx < NNODES) ? g_cnt[idx] : 0;
        sum += c[i];
    }
    s[t] = sum; __syncthreads();
    if (t == 0) {
        int r = 0;
        for (int i = 0; i < (int)blockIdx.x; i++) r += sb[i];
        s_off = r;
    }
    for (int off = 1; off < 256; off <<= 1) {
        int v = (t >= off) ? s[t - off] : 0;
        __syncthreads();
        s[t] += v;
        __syncthreads();
    }
    int excl = s[t] - sum + s_off;
#pragma unroll
    for (int i = 0; i < 4; i++) {
        int idx = base + i;
        if (idx < NNODES) {
            g_rowptr[idx] = excl;
            g_dinv[idx] = rsqrtf((float)c[i] + 1.0f);
            excl += c[i];
        }
    }
    if (blockIdx.x == 0 && t == 0) g_rowptr[NNODES] = NEDGES;
}

__global__ void k_fill(const int* __restrict__ src, const int* __restrict__ dst) {
    int e = blockIdx.x * blockDim.x + threadIdx.x;
    if (e >= NEDGES) return;
    int d = dst[e];
    int pos = atomicSub(&g_cnt[d], 1) - 1;
    g_col[g_rowptr[d] + pos] = src[e];
}

// --------------------- weight split (fp32 -> tf32 hi/lo, K-major) -----------
__global__ void k_wsplit(const float* __restrict__ W1, const float* __restrict__ W2,
                         const float* __restrict__ W3) {
    int i = blockIdx.x * 256 + threadIdx.x;
    if (i >= 24576) return;
    const float* W; int IN, OUT, idx;
    if (i < 8192)       { W = W1; IN = 128; OUT = 64;  idx = i; }
    else if (i < 16384) { W = W2; IN = 64;  OUT = 128; idx = i - 8192; }
    else                { W = W3; IN = 128; OUT = 64;  idx = i - 16384; }
    int n = idx / IN, k = idx % IN;
    float x = W[k * OUT + n];
    uint32_t hi = f2tf32(x);
    float hif = __uint_as_float(hi);
    g_Whi[i] = hif;
    g_Wlo[i] = __uint_as_float(f2tf32(x - hif));
}

// --------------------------- TF32 mma GEMM ----------------------------------
// C[:, bn0:bn0+64] += A[N x IN] @ W[bn0:bn0+64]. W pre-split hi/lo K-major.
// CTA: 128 rows x 64 cols, 128 thr = 4 warps; warp = 32 rows = 2 m16 slabs
// (B fragments shared across both slabs -> half the B smem traffic).
// A staged in 64-col K-chunks (smem fits 2-3 CTAs/SM). Packed-pair layout,
// strides 72/IN+8 (== 8 mod 32) -> conflict-free LDS.64.
template <int IN, int OUTTOT, bool SCALE, bool BIAS, bool RELU>
__global__ __launch_bounds__(128) void k_mma(
    const float* __restrict__ A,
    const float* __restrict__ Whi, const float* __restrict__ Wlo,
    const float* __restrict__ bias, float* __restrict__ C)
{
    extern __shared__ float sm[];
    constexpr int ASB = IN + 8;
    constexpr int ASA = 72;
    constexpr int NCH = IN / 64;        // K chunks
    float* sBh = sm;
    float* sBl = sm + 64 * ASB;
    float* sA  = sm + 2 * 64 * ASB;

    int t = threadIdx.x;
    int row0 = blockIdx.x * 128;
    int bn0  = blockIdx.y * 64;

    // --- stage B hi/lo (64 n-rows x IN cols), packed-pair ---
#pragma unroll
    for (int i = 0; i < (64 * IN / 4) / 128; i++) {
        int idx = t + i * 128;
        int n  = idx / (IN / 4);
        int k0 = (idx % (IN / 4)) * 4;
        float4 h = *(const float4*)&Whi[(size_t)(bn0 + n) * IN + k0];
        float4 l = *(const float4*)&Wlo[(size_t)(bn0 + n) * IN + k0];
        int off = n * ASB + (k0 >> 3) * 8 + ((k0 >> 2) & 1);
        sBh[off] = h.x; sBh[off + 2] = h.y; sBh[off + 4] = h.z; sBh[off + 6] = h.w;
        sBl[off] = l.x; sBl[off + 2] = l.y; sBl[off + 4] = l.z; sBl[off + 6] = l.w;
    }

    int lane = t & 31, warp = t >> 5;
    int g = lane >> 2, j = lane & 3;
    int wb = warp * 32;

    float c0[8][4], c1[8][4];
#pragma unroll
    for (int n = 0; n < 8; n++) {
        c0[n][0] = c0[n][1] = c0[n][2] = c0[n][3] = 0.f;
        c1[n][0] = c1[n][1] = c1[n][2] = c1[n][3] = 0.f;
    }

    const float* pA0 = &sA[(wb + g) * ASA + 2 * j];
    const float* pA1 = &sA[(wb + g + 8) * ASA + 2 * j];
    const float* pA2 = &sA[(wb + g + 16) * ASA + 2 * j];
    const float* pA3 = &sA[(wb + g + 24) * ASA + 2 * j];
    const float* pBh = &sBh[g * ASB + 2 * j];
    const float* pBl = &sBl[g * ASB + 2 * j];

    for (int ch = 0; ch < NCH; ch++) {
        // --- stage A chunk (128 rows x 64 cols), coalesced float4 ---
#pragma unroll
        for (int i = 0; i < 16; i++) {
            int idx = t + i * 128;
            int row = idx >> 4;
            int k0  = (idx & 15) * 4;
            float4 v = make_float4(0.f, 0.f, 0.f, 0.f);
            if (row0 + row < NNODES)
                v = *(const float4*)&A[(size_t)(row0 + row) * IN + ch * 64 + k0];
            int off = row * ASA + (k0 >> 3) * 8 + ((k0 >> 2) & 1);
            sA[off] = v.x; sA[off + 2] = v.y; sA[off + 4] = v.z; sA[off + 6] = v.w;
        }
        __syncthreads();

#pragma unroll
        for (int kk = 0; kk < 8; kk++) {
            int kg8 = (ch * 8 + kk) * 8;        // B col offset (packed units)
            float2 f0 = *(const float2*)(pA0 + kk * 8);
            float2 f1 = *(const float2*)(pA1 + kk * 8);
            float2 f2 = *(const float2*)(pA2 + kk * 8);
            float2 f3 = *(const float2*)(pA3 + kk * 8);
            // slab0 frags (rows g, g+8)
            uint32_t s0h0 = f2tf32(f0.x), s0h2 = f2tf32(f0.y);
            uint32_t s0h1 = f2tf32(f1.x), s0h3 = f2tf32(f1.y);
            uint32_t s0l0 = f2tf32(f0.x - __uint_as_float(s0h0));
            uint32_t s0l2 = f2tf32(f0.y - __uint_as_float(s0h2));
            uint32_t s0l1 = f2tf32(f1.x - __uint_as_float(s0h1));
            uint32_t s0l3 = f2tf32(f1.y - __uint_as_float(s0h3));
            // slab1 frags (rows g+16, g+24)
            uint32_t s1h0 = f2tf32(f2.x), s1h2 = f2tf32(f2.y);
            uint32_t s1h1 = f2tf32(f3.x), s1h3 = f2tf32(f3.y);
            uint32_t s1l0 = f2tf32(f2.x - __uint_as_float(s1h0));
            uint32_t s1l2 = f2tf32(f2.y - __uint_as_float(s1h2));
            uint32_t s1l1 = f2tf32(f3.x - __uint_as_float(s1h1));
            uint32_t s1l3 = f2tf32(f3.y - __uint_as_float(s1h3));
#pragma unroll
            for (int n = 0; n < 8; n++) {
                uint2 bh = *(const uint2*)(pBh + n * 8 * ASB + kg8);
                uint2 bl = *(const uint2*)(pBl + n * 8 * ASB + kg8);
                mma_tf32(c0[n], s0h0, s0h1, s0h2, s0h3, bh.x, bh.y);
                mma_tf32(c0[n], s0h0, s0h1, s0h2, s0h3, bl.x, bl.y);
                mma_tf32(c0[n], s0l0, s0l1, s0l2, s0l3, bh.x, bh.y);
                mma_tf32(c1[n], s1h0, s1h1, s1h2, s1h3, bh.x, bh.y);
                mma_tf32(c1[n], s1h0, s1h1, s1h2, s1h3, bl.x, bl.y);
                mma_tf32(c1[n], s1l0, s1l1, s1l2, s1l3, bh.x, bh.y);
            }
        }
        __syncthreads();
    }

    // --- epilogue: bias/relu/dinv + STG.64 ---
#pragma unroll
    for (int s = 0; s < 2; s++) {
        float (*cc)[4] = s ? c1 : c0;
        int r0 = row0 + wb + s * 16 + g, r1 = r0 + 8;
        float d0 = 1.f, d1 = 1.f;
        if (SCALE) {
            if (r0 < NNODES) d0 = g_dinv[r0];
            if (r1 < NNODES) d1 = g_dinv[r1];
        }
#pragma unroll
        for (int n = 0; n < 8; n++) {
            int col = bn0 + n * 8 + 2 * j;
            float b0 = 0.f, b1 = 0.f;
            if (BIAS) { b0 = __ldg(&bias[col]); b1 = __ldg(&bias[col + 1]); }
            float v0 = cc[n][0] + b0, v1 = cc[n][1] + b1;
            float v2 = cc[n][2] + b0, v3 = cc[n][3] + b1;
            if (RELU) {
                v0 = fmaxf(v0, 0.f); v1 = fmaxf(v1, 0.f);
                v2 = fmaxf(v2, 0.f); v3 = fmaxf(v3, 0.f);
            }
            if (SCALE) { v0 *= d0; v1 *= d0; v2 *= d1; v3 *= d1; }
            if (r0 < NNODES) *(float2*)&C[(size_t)r0 * OUTTOT + col] = make_float2(v0, v1);
            if (r1 < NNODES) *(float2*)&C[(size_t)r1 * OUTTOT + col] = make_float2(v2, v3);
        }
    }
}

// ----------------------------- Aggregation -----------------------------------
// One warp per destination node, 64-dim features (2 floats / lane).
// EDGESCALE: multiply each gathered row by dinv[s] (and self by dinv[d]).
template <bool EDGESCALE, bool BIAS, bool RELU, bool POSTSCALE>
__global__ __launch_bounds__(256) void k_agg64(
    const float* __restrict__ U, const float* __restrict__ bias,
    float* __restrict__ Out)
{
    int warp = (blockIdx.x * blockDim.x + threadIdx.x) >> 5;
    int lane = threadIdx.x & 31;
    if (warp >= NNODES) return;
    int d = warp;

    float di = g_dinv[d];
    float selfs = EDGESCALE ? di : 1.0f;
    float2 u = *(const float2*)&U[(size_t)d * 64 + 2 * lane];
    float2 acc  = make_float2(u.x * selfs, u.y * selfs);   // self loop
    float2 acc2 = make_float2(0.f, 0.f);

    int b = g_rowptr[d], e = g_rowptr[d + 1];
    int j = b;
    for (; j + 1 < e; j += 2) {
        int s0 = __ldg(&g_col[j]);
        int s1 = __ldg(&g_col[j + 1]);
        float2 v0 = *(const float2*)&U[(size_t)s0 * 64 + 2 * lane];
        float2 v1 = *(const float2*)&U[(size_t)s1 * 64 + 2 * lane];
        float w0 = EDGESCALE ? __ldg(&g_dinv[s0]) : 1.0f;
        float w1 = EDGESCALE ? __ldg(&g_dinv[s1]) : 1.0f;
        acc.x  = fmaf(v0.x, w0, acc.x);  acc.y  = fmaf(v0.y, w0, acc.y);
        acc2.x = fmaf(v1.x, w1, acc2.x); acc2.y = fmaf(v1.y, w1, acc2.y);
    }
    if (j < e) {
        int s0 = __ldg(&g_col[j]);
        float2 v0 = *(const float2*)&U[(size_t)s0 * 64 + 2 * lane];
        float w0 = EDGESCALE ? __ldg(&g_dinv[s0]) : 1.0f;
        acc.x = fmaf(v0.x, w0, acc.x); acc.y = fmaf(v0.y, w0, acc.y);
    }
    acc.x += acc2.x; acc.y += acc2.y;

    float ox = acc.x * di, oy = acc.y * di;
    if (BIAS) { ox += bias[2 * lane]; oy += bias[2 * lane + 1]; }
    if (RELU) { ox = fmaxf(ox, 0.f); oy = fmaxf(oy, 0.f); }
    if (POSTSCALE) { ox *= di; oy *= di; }
    *(float2*)&Out[(size_t)d * 64 + 2 * lane] = make_float2(ox, oy);
}

// ------------------------------- launch --------------------------------------
extern "C" void kernel_launch(void* const* d_in, const int* in_sizes, int n_in,
                              void* d_out, int out_size)
{
    const float* x  = (const float*)d_in[0];
    const int*   ei = (const int*)d_in[1];
    const float* W1 = (const float*)d_in[2];
    const float* b1 = (const float*)d_in[3];
    const float* W2 = (const float*)d_in[4];
    const float* b2 = (const float*)d_in[5];
    const float* W3 = (const float*)d_in[6];
    const float* b3 = (const float*)d_in[7];
    float* out = (float*)d_out;

    const int* src = ei;
    const int* dst = ei + NEDGES;

    float *bufA, *bufB, *buf128, *whi, *wlo;
    cudaGetSymbolAddress((void**)&bufA,   g_bufA);
    cudaGetSymbolAddress((void**)&bufB,   g_bufB);
    cudaGetSymbolAddress((void**)&buf128, g_buf128);
    cudaGetSymbolAddress((void**)&whi,    g_Whi);
    cudaGetSymbolAddress((void**)&wlo,    g_Wlo);

    const int EB = (NEDGES + 255) / 256;
    const int GB = (NNODES + 127) / 128;          // 782 GEMM row-tiles
    const int AB = (NNODES * 32 + 255) / 256;     // agg blocks

    // smem: IN=128: (2*64*136 + 128*72)*4 = 106496 -> 2 CTAs/SM
    //       IN=64:  (2*64*72  + 128*72)*4 = 73728  -> 3 CTAs/SM
    const int SM1 = (2 * 64 * 136 + 128 * 72) * 4;
    const int SM2 = (2 * 64 * 72  + 128 * 72) * 4;
    cudaFuncSetAttribute((const void*)k_mma<128, 64, false, false, false>,
                         cudaFuncAttributeMaxDynamicSharedMemorySize, SM1);
    cudaFuncSetAttribute((const void*)k_mma<64, 128, false, true, true>,
                         cudaFuncAttributeMaxDynamicSharedMemorySize, SM2);
    cudaFuncSetAttribute((const void*)k_mma<128, 64, true, false, false>,
                         cudaFuncAttributeMaxDynamicSharedMemorySize, SM1);

    // --- prep + CSR; GEMM1 kept in profiled slot #4 ---
    k_wsplit<<<96, 256>>>(W1, W2, W3);                                   // 1
    k_count<<<EB, 256>>>(dst);                                           // 2
    k_bsum<<<NB_SCAN, 256>>>();                                          // 3
    k_mma<128, 64, false, false, false><<<dim3(GB, 1), 128, SM1>>>(x, whi, wlo, nullptr, bufA); // 4
    k_writeptr<<<NB_SCAN, 256>>>();                                      // 5
    k_fill<<<EB, 256>>>(src, dst);                                       // 6

    // --- Layer 1 agg: t = relu(dinv*S(dinv_s*u1)+b1), then *dinv prescale ---
    k_agg64<true, true, true, true><<<AB, 256>>>(bufA, b1, bufB);        // 7

    // --- Layer 2: a2 = dinv*S(t*dinv); y2 = relu(a2@W2 + b2) ---
    k_agg64<false, false, false, false><<<AB, 256>>>(bufB, nullptr, bufA);               // 8
    k_mma<64, 128, false, true, true><<<dim3(GB, 2), 128, SM2>>>(bufA, whi + 8192, wlo + 8192, b2, buf128); // 9

    // --- Layer 3: u3 = dinv*(y2@W3); out = dinv*S(u3) + b3 ---
    k_mma<128, 64, true, false, false><<<dim3(GB, 1), 128, SM1>>>(buf128, whi + 16384, wlo + 16384, nullptr, bufA); // 10
    k_agg64<false, true, false, false><<<AB, 256>>>(bufA, b3, out);      // 11

    (void)in_sizes; (void)n_in; (void)out_size;
}

// round 8
// speedup vs baseline: 1.5474x; 1.3389x over previous
#include <cuda_runtime.h>
#include <cuda_fp16.h>
#include <math.h>
#include <stdint.h>
#include <string.h>

#define NNODES 100000
#define NEDGES 1600000
#define NB_SCAN 98   /* ceil(NNODES/1024) */

// ------------------------- device scratch (no allocs allowed) ---------------
__device__ int   g_cnt[NNODES];          // counts; self-zeroed by k_fill
__device__ int   g_rowptr[NNODES + 1];
__device__ int   g_col[NEDGES];
__device__ float g_dinv[NNODES];
__device__ int   g_bsums[NB_SCAN];
__device__ __align__(16) __half g_hA[(size_t)NNODES * 64];
__device__ __align__(16) __half g_hB[(size_t)NNODES * 64];
__device__ __align__(16) __half g_h128[(size_t)NNODES * 128];
// fp16-split weights, K-major [n][k], k interleaved in 16-groups for mma frags:
// L1 @0 (64x128), L2 @8192 (128x64), L3 @16384 (64x128)
__device__ __align__(16) __half g_Whi[24576];
__device__ __align__(16) __half g_Wlo[24576];

// ----------------------------- helpers --------------------------------------
__device__ __forceinline__ uint32_t h2u(__half2 h) {
    uint32_t u;
    memcpy(&u, &h, 4);
    return u;
}
__device__ __forceinline__ void mma_f16(float c[4],
    uint32_t a0, uint32_t a1, uint32_t a2, uint32_t a3,
    uint32_t b0, uint32_t b1)
{
    asm volatile("mma.sync.aligned.m16n8k16.row.col.f32.f16.f16.f32 "
        "{%0,%1,%2,%3}, {%4,%5,%6,%7}, {%8,%9}, {%0,%1,%2,%3};"
        : "+f"(c[0]), "+f"(c[1]), "+f"(c[2]), "+f"(c[3])
        : "r"(a0), "r"(a1), "r"(a2), "r"(a3), "r"(b0), "r"(b1));
}

// ------------------------------- CSR build ----------------------------------
__global__ void k_count(const int* __restrict__ dst) {
    int e = blockIdx.x * blockDim.x + threadIdx.x;
    if (e < NEDGES) atomicAdd(&g_cnt[dst[e]], 1);
}

__global__ void k_bsum() {
    __shared__ int s[256];
    int t = threadIdx.x;
    int base = blockIdx.x * 1024 + t * 4;
    int sum = 0;
#pragma unroll
    for (int i = 0; i < 4; i++) { int idx = base + i; if (idx < NNODES) sum += g_cnt[idx]; }
    s[t] = sum; __syncthreads();
    for (int off = 128; off > 0; off >>= 1) {
        if (t < off) s[t] += s[t + off];
        __syncthreads();
    }
    if (t == 0) g_bsums[blockIdx.x] = s[0];
}

__global__ void k_writeptr() {
    __shared__ int s[256];
    __shared__ int sb[NB_SCAN];
    __shared__ int s_off;
    int t = threadIdx.x;
    if (t < NB_SCAN) sb[t] = g_bsums[t];

    int base = blockIdx.x * 1024 + t * 4;
    int c[4]; int sum = 0;
#pragma unroll
    for (int i = 0; i < 4; i++) {
        int idx = base + i;
        c[i] = (idx < NNODES) ? g_cnt[idx] : 0;
        sum += c[i];
    }
    s[t] = sum; __syncthreads();
    if (t == 0) {
        int r = 0;
        for (int i = 0; i < (int)blockIdx.x; i++) r += sb[i];
        s_off = r;
    }
    for (int off = 1; off < 256; off <<= 1) {
        int v = (t >= off) ? s[t - off] : 0;
        __syncthreads();
        s[t] += v;
        __syncthreads();
    }
    int excl = s[t] - sum + s_off;
#pragma unroll
    for (int i = 0; i < 4; i++) {
        int idx = base + i;
        if (idx < NNODES) {
            g_rowptr[idx] = excl;
            g_dinv[idx] = rsqrtf((float)c[i] + 1.0f);
            excl += c[i];
        }
    }
    if (blockIdx.x == 0 && t == 0) g_rowptr[NNODES] = NEDGES;
}

__global__ void k_fill(const int* __restrict__ src, const int* __restrict__ dst) {
    int e = blockIdx.x * blockDim.x + threadIdx.x;
    if (e >= NEDGES) return;
    int d = dst[e];
    int pos = atomicSub(&g_cnt[d], 1) - 1;
    g_col[g_rowptr[d] + pos] = src[e];
}

// ------- weight split: fp32 -> fp16 hi/lo, K-major, 16-group interleaved ----
// Within each 16-k group, slot order holds k-pairs (0,1),(8,9),(2,3),(10,11),
// (4,5),(12,13),(6,7),(14,15) so a thread's mma fragment is one 8B chunk.
__global__ void k_wsplit(const float* __restrict__ W1, const float* __restrict__ W2,
                         const float* __restrict__ W3) {
    int i = blockIdx.x * 256 + threadIdx.x;
    if (i >= 24576) return;
    const float* W; int IN, OUT, idx;
    if (i < 8192)       { W = W1; IN = 128; OUT = 64;  idx = i; }
    else if (i < 16384) { W = W2; IN = 64;  OUT = 128; idx = i - 8192; }
    else                { W = W3; IN = 128; OUT = 64;  idx = i - 16384; }
    int n = idx / IN, s = idx % IN;
    int g16 = s & ~15, u = s & 15;
    int k = g16 + ((u >> 2) & 3) * 2 + ((u >> 1) & 1) * 8 + (u & 1);
    float x = W[k * OUT + n];
    __half hi = __float2half_rn(x);
    g_Whi[i] = hi;
    g_Wlo[i] = __float2half_rn(x - __half2float(hi));
}

// --------------------------- FP16 mma GEMM ----------------------------------
// C[:, bn0:bn0+64] = A[N x IN] @ W-tile (hi+lo fp16 split, 2 MMA terms).
// CTA: 128 rows x 64 cols, 128 thr = 4 warps; warp = 32 rows = 2 m16 slabs.
// Smem rows = IN+16 halves (stride == 32 mod 128 bytes -> conflict-free LDS.64).
// A stored fp16 16-group-interleaved; B pre-interleaved in global.
template <int IN, int OUTTOT, bool AFP32, bool SCALE, bool BIAS, bool RELU>
__global__ __launch_bounds__(128) void k_mma(
    const void* __restrict__ Ain,
    const __half* __restrict__ Whi, const __half* __restrict__ Wlo,
    const float* __restrict__ bias, __half* __restrict__ C)
{
    extern __shared__ __half sh[];
    constexpr int RSH = IN + 16;           // halves per smem row
    constexpr int NK16 = IN / 16;
    __half* sA  = sh;                       // 128 x RSH
    __half* sBh = sh + 128 * RSH;           // 64 x RSH
    __half* sBl = sBh + 64 * RSH;           // 64 x RSH

    int t = threadIdx.x;
    int row0 = blockIdx.x * 128;
    int bn0  = blockIdx.y * 64;

    // --- stage A ---
    if (AFP32) {
        const float* A = (const float*)Ain;
#pragma unroll
        for (int i = 0; i < IN / 8; i++) {              // 8 halves per unit
            int idx = t + i * 128;
            int row = idx / (IN / 8);
            int rem = idx % (IN / 8);
            int g16 = rem >> 1, h8 = rem & 1;
            float4 f0 = make_float4(0.f, 0.f, 0.f, 0.f), f1 = f0;
            if (row0 + row < NNODES) {
                const float* p = &A[(size_t)(row0 + row) * IN + g16 * 16 + h8 * 8];
                f0 = *(const float4*)p; f1 = *(const float4*)(p + 4);
            }
            uint32_t p0 = h2u(__floats2half2_rn(f0.x, f0.y));
            uint32_t p1 = h2u(__floats2half2_rn(f0.z, f0.w));
            uint32_t p2 = h2u(__floats2half2_rn(f1.x, f1.y));
            uint32_t p3 = h2u(__floats2half2_rn(f1.z, f1.w));
            uint32_t* dw = (uint32_t*)sA + (row * RSH + g16 * 16) / 2 + h8;
            dw[0] = p0; dw[2] = p1; dw[4] = p2; dw[6] = p3;
        }
    } else {
        const __half* A = (const __half*)Ain;
#pragma unroll
        for (int i = 0; i < IN / 16; i++) {             // full 16-group per unit
            int idx = t + i * 128;
            int row = idx / (IN / 16);
            int g16 = (idx % (IN / 16)) * 16;
            uint4 v0 = make_uint4(0, 0, 0, 0), v1 = v0;
            if (row0 + row < NNODES) {
                const uint4* p = (const uint4*)&A[(size_t)(row0 + row) * IN + g16];
                v0 = p[0]; v1 = p[1];
            }
            uint4* dw = (uint4*)((uint32_t*)sA + (row * RSH + g16) / 2);
            dw[0] = make_uint4(v0.x, v1.x, v0.y, v1.y);
            dw[1] = make_uint4(v0.z, v1.z, v0.w, v1.w);
        }
    }
    // --- stage B hi/lo (already interleaved in global; just re-stride) ---
#pragma unroll
    for (int i = 0; i < IN / 16; i++) {                 // 64*(IN/8)/128 units
        int idx = t + i * 128;
        int n  = idx / (IN / 8);
        int c8 = (idx % (IN / 8)) * 8;
        *(uint4*)((uint32_t*)sBh + (n * RSH + c8) / 2) =
            *(const uint4*)&Whi[(size_t)(bn0 + n) * IN + c8];
        *(uint4*)((uint32_t*)sBl + (n * RSH + c8) / 2) =
            *(const uint4*)&Wlo[(size_t)(bn0 + n) * IN + c8];
    }
    __syncthreads();

    int lane = t & 31, warp = t >> 5;
    int g = lane >> 2, j = lane & 3;
    int wb = warp * 32;

    float c0[8][4], c1[8][4];
#pragma unroll
    for (int n = 0; n < 8; n++) {
        c0[n][0] = c0[n][1] = c0[n][2] = c0[n][3] = 0.f;
        c1[n][0] = c1[n][1] = c1[n][2] = c1[n][3] = 0.f;
    }

    const uint32_t* sAw  = (const uint32_t*)sA;
    const uint32_t* sBhw = (const uint32_t*)sBh;
    const uint32_t* sBlw = (const uint32_t*)sBl;
    int a0w = (wb + g) * (RSH / 2) + j * 2;
    int a1w = a0w + 8 * (RSH / 2);
    int a2w = a0w + 16 * (RSH / 2);
    int a3w = a0w + 24 * (RSH / 2);
    int bw  = g * (RSH / 2) + j * 2;

#pragma unroll
    for (int kk = 0; kk < NK16; kk++) {
        int ko = kk * 8;
        uint2 r0 = *(const uint2*)&sAw[a0w + ko];   // (a0, a2) slab0
        uint2 r1 = *(const uint2*)&sAw[a1w + ko];   // (a1, a3) slab0
        uint2 r2 = *(const uint2*)&sAw[a2w + ko];   // slab1
        uint2 r3 = *(const uint2*)&sAw[a3w + ko];
#pragma unroll
        for (int n = 0; n < 8; n++) {
            uint2 bh = *(const uint2*)&sBhw[bw + n * 8 * (RSH / 2) + ko];
            uint2 bl = *(const uint2*)&sBlw[bw + n * 8 * (RSH / 2) + ko];
            mma_f16(c0[n], r0.x, r1.x, r0.y, r1.y, bh.x, bh.y);
            mma_f16(c0[n], r0.x, r1.x, r0.y, r1.y, bl.x, bl.y);
            mma_f16(c1[n], r2.x, r3.x, r2.y, r3.y, bh.x, bh.y);
            mma_f16(c1[n], r2.x, r3.x, r2.y, r3.y, bl.x, bl.y);
        }
    }

    // --- epilogue: bias/relu/dinv, pack fp16, STG.32 ---
#pragma unroll
    for (int s = 0; s < 2; s++) {
        float (*cc)[4] = s ? c1 : c0;
        int r0 = row0 + wb + s * 16 + g, r1 = r0 + 8;
        float d0 = 1.f, d1 = 1.f;
        if (SCALE) {
            if (r0 < NNODES) d0 = g_dinv[r0];
            if (r1 < NNODES) d1 = g_dinv[r1];
        }
#pragma unroll
        for (int n = 0; n < 8; n++) {
            int col = bn0 + n * 8 + 2 * j;
            float b0 = 0.f, b1 = 0.f;
            if (BIAS) { b0 = __ldg(&bias[col]); b1 = __ldg(&bias[col + 1]); }
            float v0 = cc[n][0] + b0, v1 = cc[n][1] + b1;
            float v2 = cc[n][2] + b0, v3 = cc[n][3] + b1;
            if (RELU) {
                v0 = fmaxf(v0, 0.f); v1 = fmaxf(v1, 0.f);
                v2 = fmaxf(v2, 0.f); v3 = fmaxf(v3, 0.f);
            }
            if (SCALE) { v0 *= d0; v1 *= d0; v2 *= d1; v3 *= d1; }
            if (r0 < NNODES)
                *(uint32_t*)&C[(size_t)r0 * OUTTOT + col] =
                    h2u(__floats2half2_rn(v0, v1));
            if (r1 < NNODES)
                *(uint32_t*)&C[(size_t)r1 * OUTTOT + col] =
                    h2u(__floats2half2_rn(v2, v3));
        }
    }
}

// ----------------------------- Aggregation (fp16 gather) --------------------
// One warp per destination node, 64 dims as 32 half2 (1 per lane), fp32 accum.
template <bool EDGESCALE, bool BIAS, bool RELU, bool POSTSCALE, bool OUT32>
__global__ __launch_bounds__(256) void k_agg64(
    const __half2* __restrict__ U, const float* __restrict__ bias,
    void* __restrict__ OutV)
{
    int warp = (blockIdx.x * blockDim.x + threadIdx.x) >> 5;
    int lane = threadIdx.x & 31;
    if (warp >= NNODES) return;
    int d = warp;

    float di = g_dinv[d];
    float selfs = EDGESCALE ? di : 1.0f;
    float2 u = __half22float2(U[(size_t)d * 32 + lane]);
    float2 acc  = make_float2(u.x * selfs, u.y * selfs);   // self loop
    float2 acc2 = make_float2(0.f, 0.f);

    int b = g_rowptr[d], e = g_rowptr[d + 1];
    int j = b;
    for (; j + 1 < e; j += 2) {
        int s0 = __ldg(&g_col[j]);
        int s1 = __ldg(&g_col[j + 1]);
        float2 v0 = __half22float2(__ldg(&U[(size_t)s0 * 32 + lane]));
        float2 v1 = __half22float2(__ldg(&U[(size_t)s1 * 32 + lane]));
        float w0 = EDGESCALE ? __ldg(&g_dinv[s0]) : 1.0f;
        float w1 = EDGESCALE ? __ldg(&g_dinv[s1]) : 1.0f;
        acc.x  = fmaf(v0.x, w0, acc.x);  acc.y  = fmaf(v0.y, w0, acc.y);
        acc2.x = fmaf(v1.x, w1, acc2.x); acc2.y = fmaf(v1.y, w1, acc2.y);
    }
    if (j < e) {
        int s0 = __ldg(&g_col[j]);
        float2 v0 = __half22float2(__ldg(&U[(size_t)s0 * 32 + lane]));
        float w0 = EDGESCALE ? __ldg(&g_dinv[s0]) : 1.0f;
        acc.x = fmaf(v0.x, w0, acc.x); acc.y = fmaf(v0.y, w0, acc.y);
    }
    acc.x += acc2.x; acc.y += acc2.y;

    float ox = acc.x * di, oy = acc.y * di;
    if (BIAS) {
        float2 bb = *(const float2*)&bias[2 * lane];
        ox += bb.x; oy += bb.y;
    }
    if (RELU) { ox = fmaxf(ox, 0.f); oy = fmaxf(oy, 0.f); }
    if (POSTSCALE) { ox *= di; oy *= di; }
    if (OUT32) {
        *(float2*)&((float*)OutV)[(size_t)d * 64 + 2 * lane] = make_float2(ox, oy);
    } else {
        ((__half2*)OutV)[(size_t)d * 32 + lane] = __floats2half2_rn(ox, oy);
    }
}

// ------------------------------- launch --------------------------------------
extern "C" void kernel_launch(void* const* d_in, const int* in_sizes, int n_in,
                              void* d_out, int out_size)
{
    const float* x  = (const float*)d_in[0];
    const int*   ei = (const int*)d_in[1];
    const float* W1 = (const float*)d_in[2];
    const float* b1 = (const float*)d_in[3];
    const float* W2 = (const float*)d_in[4];
    const float* b2 = (const float*)d_in[5];
    const float* W3 = (const float*)d_in[6];
    const float* b3 = (const float*)d_in[7];
    float* out = (float*)d_out;

    const int* src = ei;
    const int* dst = ei + NEDGES;

    __half *hA, *hB, *h128, *whi, *wlo;
    cudaGetSymbolAddress((void**)&hA,   g_hA);
    cudaGetSymbolAddress((void**)&hB,   g_hB);
    cudaGetSymbolAddress((void**)&h128, g_h128);
    cudaGetSymbolAddress((void**)&whi,  g_Whi);
    cudaGetSymbolAddress((void**)&wlo,  g_Wlo);

    const int EB = (NEDGES + 255) / 256;
    const int GB = (NNODES + 127) / 128;          // 782 GEMM row-tiles
    const int AB = (NNODES * 32 + 255) / 256;     // agg blocks

    // smem: IN=128: 256 rows x 144 halves x 2B = 73728 -> 3 CTAs/SM
    //       IN=64:  256 rows x  80 halves x 2B = 40960
    const int SM1 = 256 * 144 * 2;
    const int SM2 = 256 * 80 * 2;
    cudaFuncSetAttribute((const void*)k_mma<128, 64, true, false, false, false>,
                         cudaFuncAttributeMaxDynamicSharedMemorySize, SM1);
    cudaFuncSetAttribute((const void*)k_mma<64, 128, false, false, true, true>,
                         cudaFuncAttributeMaxDynamicSharedMemorySize, SM2);
    cudaFuncSetAttribute((const void*)k_mma<128, 64, false, true, false, false>,
                         cudaFuncAttributeMaxDynamicSharedMemorySize, SM1);

    // --- prep + CSR; GEMM1 kept in profiled slot #4 ---
    k_wsplit<<<96, 256>>>(W1, W2, W3);                                   // 1
    k_count<<<EB, 256>>>(dst);                                           // 2
    k_bsum<<<NB_SCAN, 256>>>();                                          // 3
    k_mma<128, 64, true, false, false, false><<<dim3(GB, 1), 128, SM1>>>(
        x, whi, wlo, nullptr, hA);                                       // 4
    k_writeptr<<<NB_SCAN, 256>>>();                                      // 5
    k_fill<<<EB, 256>>>(src, dst);                                       // 6

    // --- Layer 1 agg: t = relu(dinv*S(dinv_s*u1)+b1), then *dinv prescale ---
    k_agg64<true, true, true, true, false><<<AB, 256>>>(
        (const __half2*)hA, b1, hB);                                     // 7

    // --- Layer 2: a2 = dinv*S(prescaled t); y2 = relu(a2@W2 + b2) ---
    k_agg64<false, false, false, false, false><<<AB, 256>>>(
        (const __half2*)hB, nullptr, hA);                                // 8
    k_mma<64, 128, false, false, true, true><<<dim3(GB, 2), 128, SM2>>>(
        hA, whi + 8192, wlo + 8192, b2, h128);                           // 9

    // --- Layer 3: u3 = dinv*(y2@W3); out = dinv*S(u3) + b3 ---
    k_mma<128, 64, false, true, false, false><<<dim3(GB, 1), 128, SM1>>>(
        h128, whi + 16384, wlo + 16384, nullptr, hB);                    // 10
    k_agg64<false, true, false, false, true><<<AB, 256>>>(
        (const __half2*)hB, b3, out);                                    // 11

    (void)in_sizes; (void)n_in; (void)out_size;
}

// round 9
// speedup vs baseline: 1.6376x; 1.0583x over previous
#include <cuda_runtime.h>
#include <cuda_fp16.h>
#include <math.h>
#include <stdint.h>
#include <string.h>

#define NNODES 100000
#define NEDGES 1600000
#define NB_SCAN 98   /* ceil(NNODES/1024) */

// ------------------------- device scratch (no allocs allowed) ---------------
__device__ int   g_cnt[NNODES];          // counts; self-zeroed by k_fill
__device__ int   g_rowptr[NNODES + 1];
__device__ int   g_col[NEDGES];
__device__ float g_dinv[NNODES];
__device__ int   g_bsums[NB_SCAN];
__device__ __align__(16) __half g_hA[(size_t)NNODES * 64];
__device__ __align__(16) __half g_hB[(size_t)NNODES * 64];
__device__ __align__(16) __half g_h128[(size_t)NNODES * 128];
// fp16 weights, K-major [n][k], k interleaved in 16-groups for mma frags:
// L1 @0 (64x128), L2 @8192 (128x64), L3 @16384 (64x128)
__device__ __align__(16) __half g_Whi[24576];

// ----------------------------- helpers --------------------------------------
__device__ __forceinline__ uint32_t h2u(__half2 h) {
    uint32_t u;
    memcpy(&u, &h, 4);
    return u;
}
__device__ __forceinline__ void mma_f16(float c[4],
    uint32_t a0, uint32_t a1, uint32_t a2, uint32_t a3,
    uint32_t b0, uint32_t b1)
{
    asm volatile("mma.sync.aligned.m16n8k16.row.col.f32.f16.f16.f32 "
        "{%0,%1,%2,%3}, {%4,%5,%6,%7}, {%8,%9}, {%0,%1,%2,%3};"
        : "+f"(c[0]), "+f"(c[1]), "+f"(c[2]), "+f"(c[3])
        : "r"(a0), "r"(a1), "r"(a2), "r"(a3), "r"(b0), "r"(b1));
}

// ------------------------------- CSR build ----------------------------------
__global__ void k_count(const int* __restrict__ dst) {
    int e = blockIdx.x * blockDim.x + threadIdx.x;
    if (e < NEDGES) atomicAdd(&g_cnt[dst[e]], 1);
}

__global__ void k_bsum() {
    __shared__ int s[256];
    int t = threadIdx.x;
    int base = blockIdx.x * 1024 + t * 4;
    int sum = 0;
#pragma unroll
    for (int i = 0; i < 4; i++) { int idx = base + i; if (idx < NNODES) sum += g_cnt[idx]; }
    s[t] = sum; __syncthreads();
    for (int off = 128; off > 0; off >>= 1) {
        if (t < off) s[t] += s[t + off];
        __syncthreads();
    }
    if (t == 0) g_bsums[blockIdx.x] = s[0];
}

__global__ void k_writeptr() {
    __shared__ int s[256];
    __shared__ int sb[NB_SCAN];
    __shared__ int s_off;
    int t = threadIdx.x;
    if (t < NB_SCAN) sb[t] = g_bsums[t];

    int base = blockIdx.x * 1024 + t * 4;
    int c[4]; int sum = 0;
#pragma unroll
    for (int i = 0; i < 4; i++) {
        int idx = base + i;
        c[i] = (idx < NNODES) ? g_cnt[idx] : 0;
        sum += c[i];
    }
    s[t] = sum; __syncthreads();
    if (t == 0) {
        int r = 0;
        for (int i = 0; i < (int)blockIdx.x; i++) r += sb[i];
        s_off = r;
    }
    for (int off = 1; off < 256; off <<= 1) {
        int v = (t >= off) ? s[t - off] : 0;
        __syncthreads();
        s[t] += v;
        __syncthreads();
    }
    int excl = s[t] - sum + s_off;
#pragma unroll
    for (int i = 0; i < 4; i++) {
        int idx = base + i;
        if (idx < NNODES) {
            g_rowptr[idx] = excl;
            g_dinv[idx] = rsqrtf((float)c[i] + 1.0f);
            excl += c[i];
        }
    }
    if (blockIdx.x == 0 && t == 0) g_rowptr[NNODES] = NEDGES;
}

__global__ void k_fill(const int* __restrict__ src, const int* __restrict__ dst) {
    int e = blockIdx.x * blockDim.x + threadIdx.x;
    if (e >= NEDGES) return;
    int d = dst[e];
    int pos = atomicSub(&g_cnt[d], 1) - 1;
    g_col[g_rowptr[d] + pos] = src[e];
}

// -------- weight prep: fp32 -> fp16, K-major, 16-group interleaved ----------
// Within each 16-k group, slot order holds k-pairs (0,1),(8,9),(2,3),(10,11),
// (4,5),(12,13),(6,7),(14,15) so a thread's mma fragment is one 8B chunk.
__global__ void k_wsplit(const float* __restrict__ W1, const float* __restrict__ W2,
                         const float* __restrict__ W3) {
    int i = blockIdx.x * 256 + threadIdx.x;
    if (i >= 24576) return;
    const float* W; int IN, OUT, idx;
    if (i < 8192)       { W = W1; IN = 128; OUT = 64;  idx = i; }
    else if (i < 16384) { W = W2; IN = 64;  OUT = 128; idx = i - 8192; }
    else                { W = W3; IN = 128; OUT = 64;  idx = i - 16384; }
    int n = idx / IN, s = idx % IN;
    int g16 = s & ~15, u = s & 15;
    int k = g16 + ((u >> 2) & 3) * 2 + ((u >> 1) & 1) * 8 + (u & 1);
    g_Whi[i] = __float2half_rn(W[k * OUT + n]);
}

// --------------------------- FP16 mma GEMM ----------------------------------
// C[:, bn0:bn0+64] = A[N x IN] @ W-tile (plain fp16 W, single MMA term).
// CTA: 128 rows x 64 cols, 128 thr = 4 warps; warp = 32 rows = 2 m16 slabs.
// Smem rows = IN+16 halves (stride == 32 mod 128 bytes -> conflict-free LDS.64).
// A stored fp16 16-group-interleaved; B pre-interleaved in global.
template <int IN, int OUTTOT, bool AFP32, bool SCALE, bool BIAS, bool RELU>
__global__ __launch_bounds__(128) void k_mma(
    const void* __restrict__ Ain,
    const __half* __restrict__ Whi,
    const float* __restrict__ bias, __half* __restrict__ C)
{
    extern __shared__ __half sh[];
    constexpr int RSH = IN + 16;           // halves per smem row
    constexpr int NK16 = IN / 16;
    __half* sA  = sh;                       // 128 x RSH
    __half* sBh = sh + 128 * RSH;           // 64 x RSH

    int t = threadIdx.x;
    int row0 = blockIdx.x * 128;
    int bn0  = blockIdx.y * 64;

    // --- stage A ---
    if (AFP32) {
        const float* A = (const float*)Ain;
#pragma unroll
        for (int i = 0; i < IN / 8; i++) {              // 8 halves per unit
            int idx = t + i * 128;
            int row = idx / (IN / 8);
            int rem = idx % (IN / 8);
            int g16 = rem >> 1, h8 = rem & 1;
            float4 f0 = make_float4(0.f, 0.f, 0.f, 0.f), f1 = f0;
            if (row0 + row < NNODES) {
                const float* p = &A[(size_t)(row0 + row) * IN + g16 * 16 + h8 * 8];
                f0 = *(const float4*)p; f1 = *(const float4*)(p + 4);
            }
            uint32_t p0 = h2u(__floats2half2_rn(f0.x, f0.y));
            uint32_t p1 = h2u(__floats2half2_rn(f0.z, f0.w));
            uint32_t p2 = h2u(__floats2half2_rn(f1.x, f1.y));
            uint32_t p3 = h2u(__floats2half2_rn(f1.z, f1.w));
            uint32_t* dw = (uint32_t*)sA + (row * RSH + g16 * 16) / 2 + h8;
            dw[0] = p0; dw[2] = p1; dw[4] = p2; dw[6] = p3;
        }
    } else {
        const __half* A = (const __half*)Ain;
#pragma unroll
        for (int i = 0; i < IN / 16; i++) {             // full 16-group per unit
            int idx = t + i * 128;
            int row = idx / (IN / 16);
            int g16 = (idx % (IN / 16)) * 16;
            uint4 v0 = make_uint4(0, 0, 0, 0), v1 = v0;
            if (row0 + row < NNODES) {
                const uint4* p = (const uint4*)&A[(size_t)(row0 + row) * IN + g16];
                v0 = p[0]; v1 = p[1];
            }
            uint4* dw = (uint4*)((uint32_t*)sA + (row * RSH + g16) / 2);
            dw[0] = make_uint4(v0.x, v1.x, v0.y, v1.y);
            dw[1] = make_uint4(v0.z, v1.z, v0.w, v1.w);
        }
    }
    // --- stage B (already interleaved in global; just re-stride) ---
#pragma unroll
    for (int i = 0; i < IN / 32; i++) {                 // 64*(IN/8)/128/2 units
        int idx = t + i * 128;
        int n  = idx / (IN / 8);
        int c8 = (idx % (IN / 8)) * 8;
        *(uint4*)((uint32_t*)sBh + (n * RSH + c8) / 2) =
            *(const uint4*)&Whi[(size_t)(bn0 + n) * IN + c8];
        int idx2 = idx + 64 * (IN / 8) / 2;
        int n2  = idx2 / (IN / 8);
        int c82 = (idx2 % (IN / 8)) * 8;
        *(uint4*)((uint32_t*)sBh + (n2 * RSH + c82) / 2) =
            *(const uint4*)&Whi[(size_t)(bn0 + n2) * IN + c82];
    }
    __syncthreads();

    int lane = t & 31, warp = t >> 5;
    int g = lane >> 2, j = lane & 3;
    int wb = warp * 32;

    float c0[8][4], c1[8][4];
#pragma unroll
    for (int n = 0; n < 8; n++) {
        c0[n][0] = c0[n][1] = c0[n][2] = c0[n][3] = 0.f;
        c1[n][0] = c1[n][1] = c1[n][2] = c1[n][3] = 0.f;
    }

    const uint32_t* sAw  = (const uint32_t*)sA;
    const uint32_t* sBhw = (const uint32_t*)sBh;
    int a0w = (wb + g) * (RSH / 2) + j * 2;
    int a1w = a0w + 8 * (RSH / 2);
    int a2w = a0w + 16 * (RSH / 2);
    int a3w = a0w + 24 * (RSH / 2);
    int bw  = g * (RSH / 2) + j * 2;

#pragma unroll
    for (int kk = 0; kk < NK16; kk++) {
        int ko = kk * 8;
        uint2 r0 = *(const uint2*)&sAw[a0w + ko];   // (a0, a2) slab0
        uint2 r1 = *(const uint2*)&sAw[a1w + ko];   // (a1, a3) slab0
        uint2 r2 = *(const uint2*)&sAw[a2w + ko];   // slab1
        uint2 r3 = *(const uint2*)&sAw[a3w + ko];
#pragma unroll
        for (int n = 0; n < 8; n++) {
            uint2 bh = *(const uint2*)&sBhw[bw + n * 8 * (RSH / 2) + ko];
            mma_f16(c0[n], r0.x, r1.x, r0.y, r1.y, bh.x, bh.y);
            mma_f16(c1[n], r2.x, r3.x, r2.y, r3.y, bh.x, bh.y);
        }
    }

    // --- epilogue: bias/relu/dinv, pack fp16, STG.32 ---
#pragma unroll
    for (int s = 0; s < 2; s++) {
        float (*cc)[4] = s ? c1 : c0;
        int r0 = row0 + wb + s * 16 + g, r1 = r0 + 8;
        float d0 = 1.f, d1 = 1.f;
        if (SCALE) {
            if (r0 < NNODES) d0 = g_dinv[r0];
            if (r1 < NNODES) d1 = g_dinv[r1];
        }
#pragma unroll
        for (int n = 0; n < 8; n++) {
            int col = bn0 + n * 8 + 2 * j;
            float b0 = 0.f, b1 = 0.f;
            if (BIAS) { b0 = __ldg(&bias[col]); b1 = __ldg(&bias[col + 1]); }
            float v0 = cc[n][0] + b0, v1 = cc[n][1] + b1;
            float v2 = cc[n][2] + b0, v3 = cc[n][3] + b1;
            if (RELU) {
                v0 = fmaxf(v0, 0.f); v1 = fmaxf(v1, 0.f);
                v2 = fmaxf(v2, 0.f); v3 = fmaxf(v3, 0.f);
            }
            if (SCALE) { v0 *= d0; v1 *= d0; v2 *= d1; v3 *= d1; }
            if (r0 < NNODES)
                *(uint32_t*)&C[(size_t)r0 * OUTTOT + col] =
                    h2u(__floats2half2_rn(v0, v1));
            if (r1 < NNODES)
                *(uint32_t*)&C[(size_t)r1 * OUTTOT + col] =
                    h2u(__floats2half2_rn(v2, v3));
        }
    }
}

// ----------------------------- Aggregation (fp16 gather) --------------------
// One warp per destination node, 64 dims as 32 half2 (1 per lane), fp32 accum.
template <bool EDGESCALE, bool BIAS, bool RELU, bool POSTSCALE, bool OUT32>
__global__ __launch_bounds__(256) void k_agg64(
    const __half2* __restrict__ U, const float* __restrict__ bias,
    void* __restrict__ OutV)
{
    int warp = (blockIdx.x * blockDim.x + threadIdx.x) >> 5;
    int lane = threadIdx.x & 31;
    if (warp >= NNODES) return;
    int d = warp;

    float di = g_dinv[d];
    float selfs = EDGESCALE ? di : 1.0f;
    float2 u = __half22float2(U[(size_t)d * 32 + lane]);
    float2 acc  = make_float2(u.x * selfs, u.y * selfs);   // self loop
    float2 acc2 = make_float2(0.f, 0.f);

    int b = g_rowptr[d], e = g_rowptr[d + 1];
    int j = b;
    for (; j + 1 < e; j += 2) {
        int s0 = __ldg(&g_col[j]);
        int s1 = __ldg(&g_col[j + 1]);
        float2 v0 = __half22float2(__ldg(&U[(size_t)s0 * 32 + lane]));
        float2 v1 = __half22float2(__ldg(&U[(size_t)s1 * 32 + lane]));
        float w0 = EDGESCALE ? __ldg(&g_dinv[s0]) : 1.0f;
        float w1 = EDGESCALE ? __ldg(&g_dinv[s1]) : 1.0f;
        acc.x  = fmaf(v0.x, w0, acc.x);  acc.y  = fmaf(v0.y, w0, acc.y);
        acc2.x = fmaf(v1.x, w1, acc2.x); acc2.y = fmaf(v1.y, w1, acc2.y);
    }
    if (j < e) {
        int s0 = __ldg(&g_col[j]);
        float2 v0 = __half22float2(__ldg(&U[(size_t)s0 * 32 + lane]));
        float w0 = EDGESCALE ? __ldg(&g_dinv[s0]) : 1.0f;
        acc.x = fmaf(v0.x, w0, acc.x); acc.y = fmaf(v0.y, w0, acc.y);
    }
    acc.x += acc2.x; acc.y += acc2.y;

    float ox = acc.x * di, oy = acc.y * di;
    if (BIAS) {
        float2 bb = *(const float2*)&bias[2 * lane];
        ox += bb.x; oy += bb.y;
    }
    if (RELU) { ox = fmaxf(ox, 0.f); oy = fmaxf(oy, 0.f); }
    if (POSTSCALE) { ox *= di; oy *= di; }
    if (OUT32) {
        *(float2*)&((float*)OutV)[(size_t)d * 64 + 2 * lane] = make_float2(ox, oy);
    } else {
        ((__half2*)OutV)[(size_t)d * 32 + lane] = __floats2half2_rn(ox, oy);
    }
}

// ------------------------------- launch --------------------------------------
extern "C" void kernel_launch(void* const* d_in, const int* in_sizes, int n_in,
                              void* d_out, int out_size)
{
    const float* x  = (const float*)d_in[0];
    const int*   ei = (const int*)d_in[1];
    const float* W1 = (const float*)d_in[2];
    const float* b1 = (const float*)d_in[3];
    const float* W2 = (const float*)d_in[4];
    const float* b2 = (const float*)d_in[5];
    const float* W3 = (const float*)d_in[6];
    const float* b3 = (const float*)d_in[7];
    float* out = (float*)d_out;

    const int* src = ei;
    const int* dst = ei + NEDGES;

    __half *hA, *hB, *h128, *whi;
    cudaGetSymbolAddress((void**)&hA,   g_hA);
    cudaGetSymbolAddress((void**)&hB,   g_hB);
    cudaGetSymbolAddress((void**)&h128, g_h128);
    cudaGetSymbolAddress((void**)&whi,  g_Whi);

    const int EB = (NEDGES + 255) / 256;
    const int GB = (NNODES + 127) / 128;          // 782 GEMM row-tiles
    const int AB = (NNODES * 32 + 255) / 256;     // agg blocks

    // smem: IN=128: 192 rows x 144 halves x 2B = 55296 -> 4 CTAs/SM
    //       IN=64:  192 rows x  80 halves x 2B = 30720
    const int SM1 = 192 * 144 * 2;
    const int SM2 = 192 * 80 * 2;
    cudaFuncSetAttribute((const void*)k_mma<128, 64, true, false, false, false>,
                         cudaFuncAttributeMaxDynamicSharedMemorySize, SM1);
    cudaFuncSetAttribute((const void*)k_mma<64, 128, false, false, true, true>,
                         cudaFuncAttributeMaxDynamicSharedMemorySize, SM2);
    cudaFuncSetAttribute((const void*)k_mma<128, 64, false, true, false, false>,
                         cudaFuncAttributeMaxDynamicSharedMemorySize, SM1);

    // --- prep + CSR; GEMM1 kept in profiled slot #4 ---
    k_wsplit<<<96, 256>>>(W1, W2, W3);                                   // 1
    k_count<<<EB, 256>>>(dst);                                           // 2
    k_bsum<<<NB_SCAN, 256>>>();                                          // 3
    k_mma<128, 64, true, false, false, false><<<dim3(GB, 1), 128, SM1>>>(
        x, whi, nullptr, hA);                                            // 4
    k_writeptr<<<NB_SCAN, 256>>>();                                      // 5
    k_fill<<<EB, 256>>>(src, dst);                                       // 6

    // --- Layer 1 agg: t = relu(dinv*S(dinv_s*u1)+b1), then *dinv prescale ---
    k_agg64<true, true, true, true, false><<<AB, 256>>>(
        (const __half2*)hA, b1, hB);                                     // 7

    // --- Layer 2: a2 = dinv*S(prescaled t); y2 = relu(a2@W2 + b2) ---
    k_agg64<false, false, false, false, false><<<AB, 256>>>(
        (const __half2*)hB, nullptr, hA);                                // 8
    k_mma<64, 128, false, false, true, true><<<dim3(GB, 2), 128, SM2>>>(
        hA, whi + 8192, b2, h128);                                       // 9

    // --- Layer 3: u3 = dinv*(y2@W3); out = dinv*S(u3) + b3 ---
    k_mma<128, 64, false, true, false, false><<<dim3(GB, 1), 128, SM1>>>(
        h128, whi + 16384, nullptr, hB);                                 // 10
    k_agg64<false, true, false, false, true><<<AB, 256>>>(
        (const __half2*)hB, b3, out);                                    // 11

    (void)in_sizes; (void)n_in; (void)out_size;
}

// round 10
// speedup vs baseline: 1.6527x; 1.0092x over previous
#include <cuda_runtime.h>
#include <cuda_fp16.h>
#include <math.h>
#include <stdint.h>
#include <string.h>

#define NNODES 100000
#define NEDGES 1600000
#define NB_SCAN 98   /* ceil(NNODES/1024) */

// ------------------------- device scratch (no allocs allowed) ---------------
__device__ int   g_cnt[NNODES];          // counts; self-zeroed by k_fill4
__device__ int   g_rowptr[NNODES + 1];
__device__ int   g_col[NEDGES];
__device__ float g_dinv[NNODES];
__device__ int   g_bsums[NB_SCAN];
__device__ __align__(16) __half g_hA[(size_t)NNODES * 64];
__device__ __align__(16) __half g_hB[(size_t)NNODES * 64];
// doubles as: INTERLEAVED fp16 copy of x (launches 2-4), then y2 natural (9+)
__device__ __align__(16) __half g_h128[(size_t)NNODES * 128];
// fp16 weights, K-major [n][k], k interleaved in 16-groups for mma frags
__device__ __align__(16) __half g_Whi[24576];

// ----------------------------- helpers --------------------------------------
__device__ __forceinline__ uint32_t h2u(__half2 h) {
    uint32_t u; memcpy(&u, &h, 4); return u;
}
__device__ __forceinline__ void mma_f16(float c[4],
    uint32_t a0, uint32_t a1, uint32_t a2, uint32_t a3,
    uint32_t b0, uint32_t b1)
{
    asm volatile("mma.sync.aligned.m16n8k16.row.col.f32.f16.f16.f32 "
        "{%0,%1,%2,%3}, {%4,%5,%6,%7}, {%8,%9}, {%0,%1,%2,%3};"
        : "+f"(c[0]), "+f"(c[1]), "+f"(c[2]), "+f"(c[3])
        : "r"(a0), "r"(a1), "r"(a2), "r"(a3), "r"(b0), "r"(b1));
}

// ---------------- CSR count + x->fp16 interleaved convert (fused) -----------
__global__ void k_count_conv(const int* __restrict__ dst,
                             const float* __restrict__ x,
                             uint4* __restrict__ hX4) {
    int t = blockIdx.x * blockDim.x + threadIdx.x;
    if (t >= NEDGES) return;
    atomicAdd(&g_cnt[dst[t]], 1);
    // conversion: exactly NNODES*16 = NEDGES uint4 units, interleave applied
    int row = t >> 4, j = t & 15;
    int g16 = (j >> 1) * 16, h4 = (j & 1) * 4;
    const float* p = &x[(size_t)row * 128 + g16 + h4];
    float4 f0 = *(const float4*)p;
    float4 f1 = *(const float4*)(p + 8);
    uint4 o;
    o.x = h2u(__floats2half2_rn(f0.x, f0.y));
    o.y = h2u(__floats2half2_rn(f1.x, f1.y));
    o.z = h2u(__floats2half2_rn(f0.z, f0.w));
    o.w = h2u(__floats2half2_rn(f1.z, f1.w));
    hX4[t] = o;
}

__global__ void k_bsum() {
    __shared__ int s[256];
    int t = threadIdx.x;
    int base = blockIdx.x * 1024 + t * 4;
    int sum = 0;
#pragma unroll
    for (int i = 0; i < 4; i++) { int idx = base + i; if (idx < NNODES) sum += g_cnt[idx]; }
    s[t] = sum; __syncthreads();
    for (int off = 128; off > 0; off >>= 1) {
        if (t < off) s[t] += s[t + off];
        __syncthreads();
    }
    if (t == 0) g_bsums[blockIdx.x] = s[0];
}

__global__ void k_writeptr() {
    __shared__ int s[256];
    __shared__ int sb[NB_SCAN];
    __shared__ int s_off;
    int t = threadIdx.x;
    if (t < NB_SCAN) sb[t] = g_bsums[t];

    int base = blockIdx.x * 1024 + t * 4;
    int c[4]; int sum = 0;
#pragma unroll
    for (int i = 0; i < 4; i++) {
        int idx = base + i;
        c[i] = (idx < NNODES) ? g_cnt[idx] : 0;
        sum += c[i];
    }
    s[t] = sum; __syncthreads();
    if (t == 0) {
        int r = 0;
        for (int i = 0; i < (int)blockIdx.x; i++) r += sb[i];
        s_off = r;
    }
    for (int off = 1; off < 256; off <<= 1) {
        int v = (t >= off) ? s[t - off] : 0;
        __syncthreads();
        s[t] += v;
        __syncthreads();
    }
    int excl = s[t] - sum + s_off;
#pragma unroll
    for (int i = 0; i < 4; i++) {
        int idx = base + i;
        if (idx < NNODES) {
            g_rowptr[idx] = excl;
            g_dinv[idx] = rsqrtf((float)c[i] + 1.0f);
            excl += c[i];
        }
    }
    if (blockIdx.x == 0 && t == 0) g_rowptr[NNODES] = NEDGES;
}

__global__ void k_fill4(const int4* __restrict__ src4, const int4* __restrict__ dst4) {
    int e = blockIdx.x * blockDim.x + threadIdx.x;
    if (e >= NEDGES / 4) return;
    int4 d = dst4[e], s = src4[e];
    int p0 = atomicSub(&g_cnt[d.x], 1) - 1;
    int p1 = atomicSub(&g_cnt[d.y], 1) - 1;
    int p2 = atomicSub(&g_cnt[d.z], 1) - 1;
    int p3 = atomicSub(&g_cnt[d.w], 1) - 1;
    g_col[g_rowptr[d.x] + p0] = s.x;
    g_col[g_rowptr[d.y] + p1] = s.y;
    g_col[g_rowptr[d.z] + p2] = s.z;
    g_col[g_rowptr[d.w] + p3] = s.w;
}

// -------- weight prep: fp32 -> fp16, K-major, 16-group interleaved ----------
__global__ void k_wsplit(const float* __restrict__ W1, const float* __restrict__ W2,
                         const float* __restrict__ W3) {
    int i = blockIdx.x * 256 + threadIdx.x;
    if (i >= 24576) return;
    const float* W; int IN, OUT, idx;
    if (i < 8192)       { W = W1; IN = 128; OUT = 64;  idx = i; }
    else if (i < 16384) { W = W2; IN = 64;  OUT = 128; idx = i - 8192; }
    else                { W = W3; IN = 128; OUT = 64;  idx = i - 16384; }
    int n = idx / IN, s = idx % IN;
    int g16 = s & ~15, u = s & 15;
    int k = g16 + ((u >> 2) & 3) * 2 + ((u >> 1) & 1) * 8 + (u & 1);
    g_Whi[i] = __float2half_rn(W[k * OUT + n]);
}

// --------------------------- FP16 mma GEMM ----------------------------------
// AINT: A already interleaved in global (pure uint4 copy staging).
// else: A natural fp16; staging applies the 16-group interleave shuffle.
template <int IN, int OUTTOT, bool AINT, bool SCALE, bool BIAS, bool RELU>
__global__ __launch_bounds__(128) void k_mma(
    const __half* __restrict__ A,
    const __half* __restrict__ Whi,
    const float* __restrict__ bias, __half* __restrict__ C)
{
    extern __shared__ __half sh[];
    constexpr int RSH = IN + 16;
    constexpr int NK16 = IN / 16;
    __half* sA  = sh;                       // 128 x RSH
    __half* sBh = sh + 128 * RSH;           // 64 x RSH

    int t = threadIdx.x;
    int row0 = blockIdx.x * 128;
    int bn0  = blockIdx.y * 64;

    // --- stage A ---
    if (AINT) {
#pragma unroll
        for (int i = 0; i < IN / 8; i++) {
            int idx = t + i * 128;
            int row = idx / (IN / 8);
            int c8  = (idx % (IN / 8)) * 8;
            uint4 v = make_uint4(0, 0, 0, 0);
            if (row0 + row < NNODES)
                v = *(const uint4*)&A[(size_t)(row0 + row) * IN + c8];
            *(uint4*)((uint32_t*)sA + (row * RSH + c8) / 2) = v;
        }
    } else {
#pragma unroll
        for (int i = 0; i < IN / 16; i++) {
            int idx = t + i * 128;
            int row = idx / (IN / 16);
            int g16 = (idx % (IN / 16)) * 16;
            uint4 v0 = make_uint4(0, 0, 0, 0), v1 = v0;
            if (row0 + row < NNODES) {
                const uint4* p = (const uint4*)&A[(size_t)(row0 + row) * IN + g16];
                v0 = p[0]; v1 = p[1];
            }
            uint4* dw = (uint4*)((uint32_t*)sA + (row * RSH + g16) / 2);
            dw[0] = make_uint4(v0.x, v1.x, v0.y, v1.y);
            dw[1] = make_uint4(v0.z, v1.z, v0.w, v1.w);
        }
    }
    // --- stage B ---
#pragma unroll
    for (int i = 0; i < IN / 16; i++) {
        int idx = t + i * 128;
        int n  = idx / (IN / 8);
        int c8 = (idx % (IN / 8)) * 8;
        *(uint4*)((uint32_t*)sBh + (n * RSH + c8) / 2) =
            *(const uint4*)&Whi[(size_t)(bn0 + n) * IN + c8];
    }
    __syncthreads();

    int lane = t & 31, warp = t >> 5;
    int g = lane >> 2, j = lane & 3;
    int wb = warp * 32;

    float c0[8][4], c1[8][4];
#pragma unroll
    for (int n = 0; n < 8; n++) {
        c0[n][0] = c0[n][1] = c0[n][2] = c0[n][3] = 0.f;
        c1[n][0] = c1[n][1] = c1[n][2] = c1[n][3] = 0.f;
    }

    const uint32_t* sAw  = (const uint32_t*)sA;
    const uint32_t* sBhw = (const uint32_t*)sBh;
    int a0w = (wb + g) * (RSH / 2) + j * 2;
    int a1w = a0w + 8 * (RSH / 2);
    int a2w = a0w + 16 * (RSH / 2);
    int a3w = a0w + 24 * (RSH / 2);
    int bw  = g * (RSH / 2) + j * 2;

#pragma unroll
    for (int kk = 0; kk < NK16; kk++) {
        int ko = kk * 8;
        uint2 r0 = *(const uint2*)&sAw[a0w + ko];
        uint2 r1 = *(const uint2*)&sAw[a1w + ko];
        uint2 r2 = *(const uint2*)&sAw[a2w + ko];
        uint2 r3 = *(const uint2*)&sAw[a3w + ko];
#pragma unroll
        for (int n = 0; n < 8; n++) {
            uint2 bh = *(const uint2*)&sBhw[bw + n * 8 * (RSH / 2) + ko];
            mma_f16(c0[n], r0.x, r1.x, r0.y, r1.y, bh.x, bh.y);
            mma_f16(c1[n], r2.x, r3.x, r2.y, r3.y, bh.x, bh.y);
        }
    }

    // --- epilogue: bias/relu/dinv, pack fp16, STG.32 (natural layout) ---
#pragma unroll
    for (int s = 0; s < 2; s++) {
        float (*cc)[4] = s ? c1 : c0;
        int r0 = row0 + wb + s * 16 + g, r1 = r0 + 8;
        float d0 = 1.f, d1 = 1.f;
        if (SCALE) {
            if (r0 < NNODES) d0 = g_dinv[r0];
            if (r1 < NNODES) d1 = g_dinv[r1];
        }
#pragma unroll
        for (int n = 0; n < 8; n++) {
            int col = bn0 + n * 8 + 2 * j;
            float b0 = 0.f, b1 = 0.f;
            if (BIAS) { b0 = __ldg(&bias[col]); b1 = __ldg(&bias[col + 1]); }
            float v0 = cc[n][0] + b0, v1 = cc[n][1] + b1;
            float v2 = cc[n][2] + b0, v3 = cc[n][3] + b1;
            if (RELU) {
                v0 = fmaxf(v0, 0.f); v1 = fmaxf(v1, 0.f);
                v2 = fmaxf(v2, 0.f); v3 = fmaxf(v3, 0.f);
            }
            if (SCALE) { v0 *= d0; v1 *= d0; v2 *= d1; v3 *= d1; }
            if (r0 < NNODES)
                *(uint32_t*)&C[(size_t)r0 * OUTTOT + col] =
                    h2u(__floats2half2_rn(v0, v1));
            if (r1 < NNODES)
                *(uint32_t*)&C[(size_t)r1 * OUTTOT + col] =
                    h2u(__floats2half2_rn(v2, v3));
        }
    }
}

// ----------------------------- Aggregation (fp16 gather) --------------------
template <bool EDGESCALE, bool BIAS, bool RELU, bool POSTSCALE, bool OUT32>
__global__ __launch_bounds__(256) void k_agg64(
    const __half2* __restrict__ U, const float* __restrict__ bias,
    void* __restrict__ OutV)
{
    int warp = (blockIdx.x * blockDim.x + threadIdx.x) >> 5;
    int lane = threadIdx.x & 31;
    if (warp >= NNODES) return;
    int d = warp;

    float di = g_dinv[d];
    float selfs = EDGESCALE ? di : 1.0f;
    float2 u = __half22float2(U[(size_t)d * 32 + lane]);
    float2 acc  = make_float2(u.x * selfs, u.y * selfs);
    float2 acc2 = make_float2(0.f, 0.f);

    int b = g_rowptr[d], e = g_rowptr[d + 1];
    int j = b;
    for (; j + 1 < e; j += 2) {
        int s0 = __ldg(&g_col[j]);
        int s1 = __ldg(&g_col[j + 1]);
        float2 v0 = __half22float2(__ldg(&U[(size_t)s0 * 32 + lane]));
        float2 v1 = __half22float2(__ldg(&U[(size_t)s1 * 32 + lane]));
        float w0 = EDGESCALE ? __ldg(&g_dinv[s0]) : 1.0f;
        float w1 = EDGESCALE ? __ldg(&g_dinv[s1]) : 1.0f;
        acc.x  = fmaf(v0.x, w0, acc.x);  acc.y  = fmaf(v0.y, w0, acc.y);
        acc2.x = fmaf(v1.x, w1, acc2.x); acc2.y = fmaf(v1.y, w1, acc2.y);
    }
    if (j < e) {
        int s0 = __ldg(&g_col[j]);
        float2 v0 = __half22float2(__ldg(&U[(size_t)s0 * 32 + lane]));
        float w0 = EDGESCALE ? __ldg(&g_dinv[s0]) : 1.0f;
        acc.x = fmaf(v0.x, w0, acc.x); acc.y = fmaf(v0.y, w0, acc.y);
    }
    acc.x += acc2.x; acc.y += acc2.y;

    float ox = acc.x * di, oy = acc.y * di;
    if (BIAS) {
        float2 bb = *(const float2*)&bias[2 * lane];
        ox += bb.x; oy += bb.y;
    }
    if (RELU) { ox = fmaxf(ox, 0.f); oy = fmaxf(oy, 0.f); }
    if (POSTSCALE) { ox *= di; oy *= di; }
    if (OUT32) {
        *(float2*)&((float*)OutV)[(size_t)d * 64 + 2 * lane] = make_float2(ox, oy);
    } else {
        ((__half2*)OutV)[(size_t)d * 32 + lane] = __floats2half2_rn(ox, oy);
    }
}

// ------------------------------- launch --------------------------------------
extern "C" void kernel_launch(void* const* d_in, const int* in_sizes, int n_in,
                              void* d_out, int out_size)
{
    const float* x  = (const float*)d_in[0];
    const int*   ei = (const int*)d_in[1];
    const float* W1 = (const float*)d_in[2];
    const float* b1 = (const float*)d_in[3];
    const float* W2 = (const float*)d_in[4];
    const float* b2 = (const float*)d_in[5];
    const float* W3 = (const float*)d_in[6];
    const float* b3 = (const float*)d_in[7];
    float* out = (float*)d_out;

    const int* src = ei;
    const int* dst = ei + NEDGES;

    __half *hA, *hB, *h128, *whi;
    cudaGetSymbolAddress((void**)&hA,   g_hA);
    cudaGetSymbolAddress((void**)&hB,   g_hB);
    cudaGetSymbolAddress((void**)&h128, g_h128);
    cudaGetSymbolAddress((void**)&whi,  g_Whi);

    const int EB = (NEDGES + 255) / 256;
    const int GB = (NNODES + 127) / 128;
    const int AB = (NNODES * 32 + 255) / 256;

    const int SM1 = 192 * 144 * 2;   // 55296 -> 4 CTAs/SM
    const int SM2 = 192 * 80 * 2;    // 30720
    cudaFuncSetAttribute((const void*)k_mma<128, 64, true, false, false, false>,
                         cudaFuncAttributeMaxDynamicSharedMemorySize, SM1);
    cudaFuncSetAttribute((const void*)k_mma<64, 128, false, false, true, true>,
                         cudaFuncAttributeMaxDynamicSharedMemorySize, SM2);
    cudaFuncSetAttribute((const void*)k_mma<128, 64, false, true, false, false>,
                         cudaFuncAttributeMaxDynamicSharedMemorySize, SM1);

    // --- prep + CSR; GEMM1 kept in profiled slot #4 ---
    k_wsplit<<<96, 256>>>(W1, W2, W3);                                   // 1
    k_count_conv<<<EB, 256>>>(dst, x, (uint4*)h128);                     // 2
    k_bsum<<<NB_SCAN, 256>>>();                                          // 3
    k_mma<128, 64, true, false, false, false><<<dim3(GB, 1), 128, SM1>>>(
        h128, whi, nullptr, hA);                                         // 4
    k_writeptr<<<NB_SCAN, 256>>>();                                      // 5
    k_fill4<<<(NEDGES / 4 + 255) / 256, 256>>>(
        (const int4*)src, (const int4*)dst);                             // 6

    // --- Layer 1 agg ---
    k_agg64<true, true, true, true, false><<<AB, 256>>>(
        (const __half2*)hA, b1, hB);                                     // 7

    // --- Layer 2 ---
    k_agg64<false, false, false, false, false><<<AB, 256>>>(
        (const __half2*)hB, nullptr, hA);                                // 8
    k_mma<64, 128, false, false, true, true><<<dim3(GB, 2), 128, SM2>>>(
        hA, whi + 8192, b2, h128);                                       // 9

    // --- Layer 3 ---
    k_mma<128, 64, false, true, false, false><<<dim3(GB, 1), 128, SM1>>>(
        h128, whi + 16384, nullptr, hB);                                 // 10
    k_agg64<false, true, false, false, true><<<AB, 256>>>(
        (const __half2*)hB, b3, out);                                    // 11

    (void)in_sizes; (void)n_in; (void)out_size;
}